// round 14
// baseline (speedup 1.0000x reference)
#include <cuda_runtime.h>
#include <cuda_fp16.h>
#include <math.h>
#include <stdint.h>

#define L_TOT 1568
#define T_LEN 784
#define D_MODEL 768
#define N_HEADS 12
#define DIM_HEAD 64
#define D_FF 3072
#define BATCH 4
#define ROWS (BATCH * L_TOT)          // 6272
#define NPATCH 196

// ---------------- scratch ----------------
__device__ float  g_xaug[ROWS * D_MODEL];          // residual stream (f32)
__device__ __half g_h[ROWS * D_MODEL];             // ln_att output (h16)
__device__ __half g_qkv[ROWS * 3 * D_MODEL];       // qkv (h16)
__device__ __half g_ctx[ROWS * D_MODEL];           // attention context (h16)
__device__ __half g_y2[ROWS * D_MODEL];            // ln2 output (h16)
__device__ __half g_ff[ROWS * D_FF];               // ff hidden (h16)
__device__ __half g_whalf[7077888];                // wqkv|wout|w1|w2 in h16

// ---------------- helpers ----------------
__device__ __forceinline__ unsigned smem_u32(const void* p) {
    unsigned r;
    asm("{ .reg .u64 t; cvta.to.shared.u64 t, %1; cvt.u32.u64 %0, t; }" : "=r"(r) : "l"(p));
    return r;
}
__device__ __forceinline__ void cp16(unsigned dst, const void* src, bool valid) {
    int sz = valid ? 16 : 0;
    asm volatile("cp.async.cg.shared.global [%0], [%1], 16, %2;" :: "r"(dst), "l"(src), "r"(sz));
}
__device__ __forceinline__ void mma_f16(float4& d, const unsigned a[4], unsigned b0, unsigned b1) {
    asm volatile(
        "mma.sync.aligned.m16n8k16.row.col.f32.f16.f16.f32 "
        "{%0,%1,%2,%3}, {%4,%5,%6,%7}, {%8,%9}, {%0,%1,%2,%3};"
        : "+f"(d.x), "+f"(d.y), "+f"(d.z), "+f"(d.w)
        : "r"(a[0]), "r"(a[1]), "r"(a[2]), "r"(a[3]), "r"(b0), "r"(b1));
}
__device__ __forceinline__ void ldmx4(unsigned& r0, unsigned& r1, unsigned& r2, unsigned& r3,
                                      unsigned addr) {
    asm volatile("ldmatrix.sync.aligned.m8n8.x4.shared.b16 {%0,%1,%2,%3}, [%4];"
                 : "=r"(r0), "=r"(r1), "=r"(r2), "=r"(r3) : "r"(addr));
}
__device__ __forceinline__ void ldmx4t(unsigned& r0, unsigned& r1, unsigned& r2, unsigned& r3,
                                       unsigned addr) {
    asm volatile("ldmatrix.sync.aligned.m8n8.x4.trans.shared.b16 {%0,%1,%2,%3}, [%4];"
                 : "=r"(r0), "=r"(r1), "=r"(r2), "=r"(r3) : "r"(addr));
}

// ---------------- fp16 tensor-core GEMM (ldmatrix fragments) ----------------
// C[m,n] = sum_k A[m,k] * B[n,k]  (A [M,K] h16 row-major, B [N,K] h16 row-major)
#define SH 40   // smem row stride in halves (32 data + 8 pad)
template <bool BIAS, bool RES, bool SILU, bool OUTW, bool HOUT>
__global__ void __launch_bounds__(256, 1)
hgemm(const __half* __restrict__ A, const __half* __restrict__ B,
      void* __restrict__ Cv, const float* __restrict__ bias, const float* __restrict__ res,
      float* __restrict__ out2,
      int M, int N, int K, int lda, int ldb, int ldc) {
    const int NT = 8;
    __shared__ __half As[2][128 * SH];
    __shared__ __half Bs[2][128 * SH];

    int tid = threadIdx.x;
    int m0 = blockIdx.y * 128, n0 = blockIdx.x * 128;
    int warp = tid >> 5, lane = tid & 31;
    int wm = warp & 3, wn = warp >> 2;
    int mw = m0 + wm * 32;
    int nw = n0 + wn * 64;
    int g = lane >> 2, tg = lane & 3;

    float4 acc[2][NT];
    #pragma unroll
    for (int i = 0; i < 2; i++)
        #pragma unroll
        for (int j = 0; j < NT; j++) acc[i][j] = make_float4(0.f, 0.f, 0.f, 0.f);

    unsigned sA = smem_u32(As), sB = smem_u32(Bs);

    // ldmatrix lane offsets (in halves)
    int alm = ((lane & 7) + ((lane >> 3) & 1) * 8) * SH + (lane >> 4) * 8;
    int blm = ((lane & 7) + ((lane >> 4) & 1) * 8) * SH + ((lane >> 3) & 1) * 8;

    auto load_stage = [&](int ks, int buf) {
        #pragma unroll
        for (int i = 0; i < 2; i++) {
            int c = tid + i * 256;
            int row = c >> 2, kc = (c & 3) << 3;
            unsigned dst = sA + (buf * 128 * SH + row * SH + kc) * 2;
            cp16(dst, A + (long long)(m0 + row) * lda + ks + kc, true);
        }
        #pragma unroll
        for (int i = 0; i < 2; i++) {
            int c = tid + i * 256;
            int row = c >> 2, kc = (c & 3) << 3;
            unsigned dst = sB + (buf * 128 * SH + row * SH + kc) * 2;
            cp16(dst, B + (long long)(n0 + row) * ldb + ks + kc, true);
        }
    };

    auto compute = [&](int buf) {
        unsigned abase = sA + (buf * 128 * SH + wm * 32 * SH + alm) * 2;
        unsigned bbase = sB + (buf * 128 * SH + wn * 64 * SH + blm) * 2;
        #pragma unroll
        for (int ks = 0; ks < 2; ks++) {
            unsigned af[2][4];
            ldmx4(af[0][0], af[0][1], af[0][2], af[0][3], abase + (ks * 16) * 2);
            ldmx4(af[1][0], af[1][1], af[1][2], af[1][3], abase + (16 * SH + ks * 16) * 2);
            #pragma unroll
            for (int j0 = 0; j0 < NT; j0 += 2) {
                unsigned b0, b1, b2, b3;
                ldmx4(b0, b1, b2, b3, bbase + (8 * j0 * SH + ks * 16) * 2);
                mma_f16(acc[0][j0], af[0], b0, b1);
                mma_f16(acc[1][j0], af[1], b0, b1);
                mma_f16(acc[0][j0 + 1], af[0], b2, b3);
                mma_f16(acc[1][j0 + 1], af[1], b2, b3);
            }
        }
    };

    int numK = K >> 5;
    load_stage(0, 0);
    asm volatile("cp.async.commit_group;");
    for (int it = 0; it < numK; it++) {
        if (it + 1 < numK) {
            load_stage((it + 1) << 5, (it + 1) & 1);
            asm volatile("cp.async.commit_group;");
            asm volatile("cp.async.wait_group 1;");
        } else {
            asm volatile("cp.async.wait_group 0;");
        }
        __syncthreads();
        compute(it & 1);
        __syncthreads();
    }

    float* Cf = (float*)Cv;
    __half* Ch = (__half*)Cv;
    #pragma unroll
    for (int i = 0; i < 2; i++) {
        #pragma unroll
        for (int half_ = 0; half_ < 2; half_++) {
            int r = mw + i * 16 + g + half_ * 8;
            long long base = (long long)r * ldc;
            int bb = 0, l = 0;
            if (OUTW) { bb = r / L_TOT; l = r - bb * L_TOT; }
            #pragma unroll
            for (int j = 0; j < NT; j++) {
                float w0 = half_ ? acc[i][j].z : acc[i][j].x;
                float w1 = half_ ? acc[i][j].w : acc[i][j].y;
                int c0 = nw + j * 8 + tg * 2;
                if (BIAS) { w0 += bias[c0]; w1 += bias[c0 + 1]; }
                if (SILU) {
                    w0 = w0 / (1.f + __expf(-w0));
                    w1 = w1 / (1.f + __expf(-w1));
                }
                if (RES) { w0 += res[base + c0]; w1 += res[base + c0 + 1]; }
                if (HOUT) {
                    *(__half2*)(Ch + base + c0) = __floats2half2_rn(w0, w1);
                } else {
                    Cf[base + c0] = w0;
                    Cf[base + c0 + 1] = w1;
                }
                if (OUTW && l >= T_LEN) {
                    long long ob = ((long long)bb * T_LEN + (l - T_LEN)) * D_MODEL;
                    out2[ob + c0] = w0;
                    out2[ob + c0 + 1] = w1;
                }
            }
        }
    }
}

// ---------------- fused weight f32 -> f16 conversion ----------------
__global__ void cvt_all_kernel(const float* __restrict__ wqkv, const float* __restrict__ wout,
                               const float* __restrict__ w1, const float* __restrict__ w2,
                               __half* __restrict__ dst) {
    const int N0 = 884736, N1 = 294912, N2 = 1179648;
    const int E1 = N0 + N1, E2 = E1 + N2, TOT = E2 + N2;
    for (int i = blockIdx.x * 256 + threadIdx.x; i < TOT; i += gridDim.x * 256) {
        const float* src;
        int off;
        if (i < N0)        { src = wqkv; off = i; }
        else if (i < E1)   { src = wout; off = i - N0; }
        else if (i < E2)   { src = w1;   off = i - E1; }
        else               { src = w2;   off = i - E2; }
        float2 v = ((const float2*)src)[off];
        ((__half2*)dst)[i] = __floats2half2_rn(v.x, v.y);
    }
}

// ---------------- fused flash attention (fp16 mma, ldmatrix for K & PV) ----------------
#define PADH 72
__global__ void __launch_bounds__(256, 2)
flash_attn(const __half* __restrict__ qkv, __half* __restrict__ ctx) {
    extern __shared__ __half smh[];
    __half* sP = smh;                       // 128 * PADH
    __half* sK = smh + 128 * PADH;          // 2 * 64 * PADH
    __half* sV = sK + 2 * 64 * PADH;        // 2 * 64 * PADH

    int tid = threadIdx.x;
    int warp = tid >> 5, lane = tid & 31;
    int g = lane >> 2, tg = lane & 3;
    int bh = blockIdx.y;
    int b = bh / N_HEADS, h = bh - b * N_HEADS;
    int m0 = blockIdx.x * 128;

    const __half* base = qkv + (long long)b * L_TOT * (3 * D_MODEL);
    const __half* Qp = base + h * 64;
    const __half* Kp = base + D_MODEL + h * 64;
    const __half* Vp = base + 2 * D_MODEL + h * 64;

    #pragma unroll
    for (int i = 0; i < 4; i++) {
        int c = tid + i * 256;
        int m = c >> 3, q = (c & 7) << 3;
        unsigned dst = smem_u32(sP + m * PADH + q);
        cp16(dst, Qp + (long long)(m0 + m) * (3 * D_MODEL) + q, (m0 + m) < L_TOT);
    }
    asm volatile("cp.async.commit_group;");
    asm volatile("cp.async.wait_group 0;");
    __syncthreads();

    unsigned qf[4][4];
    {
        const __half* qp = sP + (warp * 16) * PADH;
        #pragma unroll
        for (int ks = 0; ks < 4; ks++) {
            const __half* p = qp + g * PADH + 16 * ks + 2 * tg;
            qf[ks][0] = *(const unsigned*)p;
            qf[ks][1] = *(const unsigned*)(p + 8 * PADH);
            qf[ks][2] = *(const unsigned*)(p + 8);
            qf[ks][3] = *(const unsigned*)(p + 8 * PADH + 8);
        }
    }
    __syncthreads();

    int r0 = m0 + warp * 16 + g;
    int r1 = r0 + 8;
    int km0 = (r0 < T_LEN) ? L_TOT : ((r0 / NPATCH) + 1) * NPATCH;
    int km1 = (r1 < T_LEN) ? L_TOT : ((r1 / NPATCH) + 1) * NPATCH;

    float mrow0 = -1e30f, mrow1 = -1e30f, lrow0 = 0.f, lrow1 = 0.f;
    float4 accO[8];
    #pragma unroll
    for (int j = 0; j < 8; j++) accO[j] = make_float4(0.f, 0.f, 0.f, 0.f);

    int rlast = min(m0 + 127, L_TOT - 1);
    int kend = (m0 < T_LEN) ? L_TOT : ((rlast / NPATCH) + 1) * NPATCH;
    int ntiles = (kend + 63) >> 6;

    auto loadKV = [&](int t, int buf) {
        int n0t = t * 64;
        #pragma unroll
        for (int i = 0; i < 2; i++) {
            int c = tid + i * 256;
            int kv = c >> 3, q = (c & 7) << 3;
            bool ok = (n0t + kv) < L_TOT;
            long long goff = (long long)(n0t + kv) * (3 * D_MODEL) + q;
            cp16(smem_u32(sK + buf * 64 * PADH + kv * PADH + q), Kp + goff, ok);
            cp16(smem_u32(sV + buf * 64 * PADH + kv * PADH + q), Vp + goff, ok);
        }
    };

    loadKV(0, 0);
    asm volatile("cp.async.commit_group;");

    __half* pp = sP + (warp * 16) * PADH;
    int pa_off = ((lane & 7) + ((lane >> 3) & 1) * 8) * PADH + (lane >> 4) * 8;
    int vb_off = (lane & 15) * PADH + (lane >> 4) * 8;
    int kb_off = ((lane & 7) + ((lane >> 4) & 1) * 8) * PADH + ((lane >> 3) & 1) * 8;

    for (int t = 0; t < ntiles; t++) {
        int buf = t & 1;
        if (t + 1 < ntiles) {
            loadKV(t + 1, buf ^ 1);
            asm volatile("cp.async.commit_group;");
            asm volatile("cp.async.wait_group 1;");
        } else {
            asm volatile("cp.async.wait_group 0;");
        }
        __syncthreads();

        // S = Q @ K^T
        float4 s[8];
        #pragma unroll
        for (int j = 0; j < 8; j++) s[j] = make_float4(0.f, 0.f, 0.f, 0.f);
        unsigned kaddr = smem_u32(sK + buf * 64 * PADH) + kb_off * 2;
        #pragma unroll
        for (int ks = 0; ks < 4; ks++) {
            #pragma unroll
            for (int j0 = 0; j0 < 8; j0 += 2) {
                unsigned b0, b1, b2, b3;
                ldmx4(b0, b1, b2, b3, kaddr + (8 * j0 * PADH + 16 * ks) * 2);
                mma_f16(s[j0], qf[ks], b0, b1);
                mma_f16(s[j0 + 1], qf[ks], b2, b3);
            }
        }

        // scale + mask + online softmax
        float tmax0 = -1e30f, tmax1 = -1e30f;
        #pragma unroll
        for (int j = 0; j < 8; j++) {
            int c0 = t * 64 + 8 * j + 2 * tg;
            int c1 = c0 + 1;
            s[j].x = (c0 < km0) ? s[j].x * 0.125f : -1e30f;
            s[j].y = (c1 < km0) ? s[j].y * 0.125f : -1e30f;
            s[j].z = (c0 < km1) ? s[j].z * 0.125f : -1e30f;
            s[j].w = (c1 < km1) ? s[j].w * 0.125f : -1e30f;
            tmax0 = fmaxf(tmax0, fmaxf(s[j].x, s[j].y));
            tmax1 = fmaxf(tmax1, fmaxf(s[j].z, s[j].w));
        }
        tmax0 = fmaxf(tmax0, __shfl_xor_sync(0xffffffffu, tmax0, 1));
        tmax0 = fmaxf(tmax0, __shfl_xor_sync(0xffffffffu, tmax0, 2));
        tmax1 = fmaxf(tmax1, __shfl_xor_sync(0xffffffffu, tmax1, 1));
        tmax1 = fmaxf(tmax1, __shfl_xor_sync(0xffffffffu, tmax1, 2));

        float mn0 = fmaxf(mrow0, tmax0), mn1 = fmaxf(mrow1, tmax1);
        float al0 = __expf(mrow0 - mn0), al1 = __expf(mrow1 - mn1);
        mrow0 = mn0; mrow1 = mn1;

        float rs0 = 0.f, rs1 = 0.f;
        #pragma unroll
        for (int j = 0; j < 8; j++) {
            s[j].x = __expf(s[j].x - mn0);
            s[j].y = __expf(s[j].y - mn0);
            s[j].z = __expf(s[j].z - mn1);
            s[j].w = __expf(s[j].w - mn1);
            rs0 += s[j].x + s[j].y;
            rs1 += s[j].z + s[j].w;
            *(__half2*)&pp[g * PADH + 8 * j + 2 * tg] = __floats2half2_rn(s[j].x, s[j].y);
            *(__half2*)&pp[(g + 8) * PADH + 8 * j + 2 * tg] = __floats2half2_rn(s[j].z, s[j].w);
        }
        rs0 += __shfl_xor_sync(0xffffffffu, rs0, 1);
        rs0 += __shfl_xor_sync(0xffffffffu, rs0, 2);
        rs1 += __shfl_xor_sync(0xffffffffu, rs1, 1);
        rs1 += __shfl_xor_sync(0xffffffffu, rs1, 2);
        lrow0 = lrow0 * al0 + rs0;
        lrow1 = lrow1 * al1 + rs1;

        #pragma unroll
        for (int j = 0; j < 8; j++) {
            accO[j].x *= al0; accO[j].y *= al0;
            accO[j].z *= al1; accO[j].w *= al1;
        }
        __syncwarp();

        // O += P @ V via ldmatrix
        unsigned paddr = smem_u32(pp) + pa_off * 2;
        unsigned vaddr = smem_u32(sV + buf * 64 * PADH) + vb_off * 2;
        #pragma unroll
        for (int ks = 0; ks < 4; ks++) {
            unsigned af[4];
            ldmx4(af[0], af[1], af[2], af[3], paddr + 16 * ks * 2);
            #pragma unroll
            for (int jp = 0; jp < 4; jp++) {
                unsigned b0, b1, b2, b3;
                ldmx4t(b0, b1, b2, b3, vaddr + (16 * ks * PADH + 16 * jp) * 2);
                mma_f16(accO[2 * jp], af, b0, b1);
                mma_f16(accO[2 * jp + 1], af, b2, b3);
            }
        }
        __syncthreads();
    }

    float inv0 = 1.f / lrow0, inv1 = 1.f / lrow1;
    if (r0 < L_TOT) {
        __half* op = ctx + ((long long)b * L_TOT + r0) * D_MODEL + h * 64;
        #pragma unroll
        for (int j = 0; j < 8; j++)
            *(__half2*)&op[8 * j + 2 * tg] = __floats2half2_rn(accO[j].x * inv0, accO[j].y * inv0);
    }
    if (r1 < L_TOT) {
        __half* op = ctx + ((long long)b * L_TOT + r1) * D_MODEL + h * 64;
        #pragma unroll
        for (int j = 0; j < 8; j++)
            *(__half2*)&op[8 * j + 2 * tg] = __floats2half2_rn(accO[j].z * inv1, accO[j].w * inv1);
    }
}

// ---------------- layernorms: warp per row, shuffle reductions ----------------
__device__ __forceinline__ float wred(float v) {
    #pragma unroll
    for (int s = 16; s; s >>= 1) v += __shfl_xor_sync(0xffffffffu, v, s);
    return v;
}

__global__ void ln_build_kernel(const float* __restrict__ x,
                                const float* __restrict__ mem,
                                const float* __restrict__ g1, const float* __restrict__ b1,
                                const float* __restrict__ ga, const float* __restrict__ ba) {
    int warp = threadIdx.x >> 5, lane = threadIdx.x & 31;
    int row = blockIdx.x * 8 + warp;
    int b = row / L_TOT;
    int l = row - b * L_TOT;
    const float* src = (l < T_LEN)
        ? mem + ((long long)b * 1024 + l) * D_MODEL
        : x   + ((long long)b * T_LEN + (l - T_LEN)) * D_MODEL;

    float4 v[6];
    float sum = 0.f, sq = 0.f;
    #pragma unroll
    for (int i = 0; i < 6; i++) {
        v[i] = ((const float4*)src)[lane + 32 * i];
        sum += v[i].x + v[i].y + v[i].z + v[i].w;
        sq += v[i].x * v[i].x + v[i].y * v[i].y + v[i].z * v[i].z + v[i].w * v[i].w;
    }
    sum = wred(sum); sq = wred(sq);
    float mu = sum * (1.f / 768.f);
    float var = sq * (1.f / 768.f) - mu * mu;
    float rstd = rsqrtf(var + 1e-5f);

    float* xrow = g_xaug + (long long)row * D_MODEL;
    float w[6][4];
    float s2 = 0.f, q2 = 0.f;
    #pragma unroll
    for (int i = 0; i < 6; i++) {
        int c = (lane + 32 * i) * 4;
        float4 gv = *(const float4*)(g1 + c);
        float4 bv = *(const float4*)(b1 + c);
        w[i][0] = (v[i].x - mu) * rstd * gv.x + bv.x;
        w[i][1] = (v[i].y - mu) * rstd * gv.y + bv.y;
        w[i][2] = (v[i].z - mu) * rstd * gv.z + bv.z;
        w[i][3] = (v[i].w - mu) * rstd * gv.w + bv.w;
        *(float4*)(xrow + c) = make_float4(w[i][0], w[i][1], w[i][2], w[i][3]);
        s2 += w[i][0] + w[i][1] + w[i][2] + w[i][3];
        q2 += w[i][0] * w[i][0] + w[i][1] * w[i][1] + w[i][2] * w[i][2] + w[i][3] * w[i][3];
    }
    s2 = wred(s2); q2 = wred(q2);
    float mu2 = s2 * (1.f / 768.f);
    float var2 = q2 * (1.f / 768.f) - mu2 * mu2;
    float rstd2 = rsqrtf(var2 + 1e-5f);

    __half* hrow = g_h + (long long)row * D_MODEL;
    #pragma unroll
    for (int i = 0; i < 6; i++) {
        int c = (lane + 32 * i) * 4;
        float4 gv = *(const float4*)(ga + c);
        float4 bv = *(const float4*)(ba + c);
        __half2 h0 = __floats2half2_rn((w[i][0] - mu2) * rstd2 * gv.x + bv.x,
                                       (w[i][1] - mu2) * rstd2 * gv.y + bv.y);
        __half2 h1 = __floats2half2_rn((w[i][2] - mu2) * rstd2 * gv.z + bv.z,
                                       (w[i][3] - mu2) * rstd2 * gv.w + bv.w);
        *(__half2*)(hrow + c) = h0;
        *(__half2*)(hrow + c + 2) = h1;
    }
}

__global__ void ln_kernel(const float* __restrict__ src, __half* __restrict__ dst,
                          const float* __restrict__ g, const float* __restrict__ b) {
    int warp = threadIdx.x >> 5, lane = threadIdx.x & 31;
    int row = blockIdx.x * 8 + warp;
    const float* p = src + (long long)row * D_MODEL;

    float4 v[6];
    float sum = 0.f, sq = 0.f;
    #pragma unroll
    for (int i = 0; i < 6; i++) {
        v[i] = ((const float4*)p)[lane + 32 * i];
        sum += v[i].x + v[i].y + v[i].z + v[i].w;
        sq += v[i].x * v[i].x + v[i].y * v[i].y + v[i].z * v[i].z + v[i].w * v[i].w;
    }
    sum = wred(sum); sq = wred(sq);
    float mu = sum * (1.f / 768.f);
    float var = sq * (1.f / 768.f) - mu * mu;
    float rstd = rsqrtf(var + 1e-5f);

    __half* drow = dst + (long long)row * D_MODEL;
    #pragma unroll
    for (int i = 0; i < 6; i++) {
        int c = (lane + 32 * i) * 4;
        float4 gv = *(const float4*)(g + c);
        float4 bv = *(const float4*)(b + c);
        __half2 h0 = __floats2half2_rn((v[i].x - mu) * rstd * gv.x + bv.x,
                                       (v[i].y - mu) * rstd * gv.y + bv.y);
        __half2 h1 = __floats2half2_rn((v[i].z - mu) * rstd * gv.z + bv.z,
                                       (v[i].w - mu) * rstd * gv.w + bv.w);
        *(__half2*)(drow + c) = h0;
        *(__half2*)(drow + c + 2) = h1;
    }
}

// ---------------- launch ----------------
extern "C" void kernel_launch(void* const* d_in, const int* in_sizes, int n_in,
                              void* d_out, int out_size) {
    const float* x        = (const float*)d_in[0];
    const float* memory   = (const float*)d_in[1];
    const float* ln_att_g = (const float*)d_in[2];
    const float* ln_att_b = (const float*)d_in[3];
    const float* w_qkv    = (const float*)d_in[4];
    const float* w_out    = (const float*)d_in[5];
    const float* b_out    = (const float*)d_in[6];
    const float* ln1_g    = (const float*)d_in[7];
    const float* ln1_b    = (const float*)d_in[8];
    const float* ln2_g    = (const float*)d_in[9];
    const float* ln2_b    = (const float*)d_in[10];
    const float* w1       = (const float*)d_in[11];
    const float* b1       = (const float*)d_in[12];
    const float* w2       = (const float*)d_in[13];
    const float* b2       = (const float*)d_in[14];
    float* out = (float*)d_out;

    float* xaug;
    __half *h, *qkv, *ctx, *y2, *ff, *wh;
    cudaGetSymbolAddress((void**)&xaug, g_xaug);
    cudaGetSymbolAddress((void**)&h,    g_h);
    cudaGetSymbolAddress((void**)&qkv,  g_qkv);
    cudaGetSymbolAddress((void**)&ctx,  g_ctx);
    cudaGetSymbolAddress((void**)&y2,   g_y2);
    cudaGetSymbolAddress((void**)&ff,   g_ff);
    cudaGetSymbolAddress((void**)&wh,   g_whalf);

    __half* wqkv_h = wh;
    __half* wout_h = wh + 1769472;
    __half* w1_h   = wh + 2359296;
    __half* w2_h   = wh + 4718592;

    const int FLASH_SMEM = (128 * PADH + 4 * 64 * PADH) * 2;  // 55296 B
    cudaFuncSetAttribute(flash_attn, cudaFuncAttributeMaxDynamicSharedMemorySize, FLASH_SMEM);

    // 0) convert all weights to h16
    cvt_all_kernel<<<2048, 256>>>(w_qkv, w_out, w1, w2, wh);

    // 1) x_aug = ln1(concat(mem, x)) [f32]; h = ln_att(x_aug) [h16]
    ln_build_kernel<<<784, 256>>>(x, memory, ln1_g, ln1_b, ln_att_g, ln_att_b);

    // 2) qkv = h @ w_qkv^T  [h16]
    hgemm<false, false, false, false, true><<<dim3(18, 49), 256>>>(
        h, wqkv_h, qkv, nullptr, nullptr, nullptr,
        ROWS, 3 * D_MODEL, D_MODEL, D_MODEL, D_MODEL, 3 * D_MODEL);

    // 3-5) fused attention -> ctx [h16]
    flash_attn<<<dim3(13, 48), 256, FLASH_SMEM>>>(qkv, ctx);

    // 6) xaug += ctx @ w_out^T + b_out  [f32]
    hgemm<true, true, false, false, false><<<dim3(6, 49), 256>>>(
        ctx, wout_h, xaug, b_out, xaug, nullptr,
        ROWS, D_MODEL, D_MODEL, D_MODEL, D_MODEL, D_MODEL);

    // 7) y2 = ln2(xaug)  [h16]
    ln_kernel<<<784, 256>>>(xaug, y2, ln2_g, ln2_b);

    // 8) ff = silu(y2 @ w1^T + b1)  [h16]
    hgemm<true, false, true, false, true><<<dim3(24, 49), 256>>>(
        y2, w1_h, ff, b1, nullptr, nullptr,
        ROWS, D_FF, D_MODEL, D_MODEL, D_MODEL, D_FF);

    // 9) xaug += ff @ w2^T + b2 ; scatter x-rows to out  [f32]
    hgemm<true, true, false, true, false><<<dim3(6, 49), 256>>>(
        ff, w2_h, xaug, b2, xaug, out,
        ROWS, D_MODEL, D_FF, D_FF, D_FF, D_MODEL);
}

// round 15
// speedup vs baseline: 1.1300x; 1.1300x over previous
#include <cuda_runtime.h>
#include <cuda_fp16.h>
#include <math.h>
#include <stdint.h>

#define L_TOT 1568
#define T_LEN 784
#define D_MODEL 768
#define N_HEADS 12
#define DIM_HEAD 64
#define D_FF 3072
#define BATCH 4
#define ROWS (BATCH * L_TOT)          // 6272
#define NPATCH 196

// ---------------- scratch ----------------
__device__ float  g_xaug[ROWS * D_MODEL];          // residual stream (f32)
__device__ __half g_h[ROWS * D_MODEL];             // ln_att output (h16)
__device__ __half g_qkv[ROWS * 3 * D_MODEL];       // qkv (h16)
__device__ __half g_ctx[ROWS * D_MODEL];           // attention context (h16)
__device__ __half g_y2[ROWS * D_MODEL];            // ln2 output (h16)
__device__ __half g_ff[ROWS * D_FF];               // ff hidden (h16)
__device__ __half g_whalf[7077888];                // wqkv|wout|w1|w2 in h16

// ---------------- helpers ----------------
__device__ __forceinline__ unsigned smem_u32(const void* p) {
    unsigned r;
    asm("{ .reg .u64 t; cvta.to.shared.u64 t, %1; cvt.u32.u64 %0, t; }" : "=r"(r) : "l"(p));
    return r;
}
__device__ __forceinline__ void cp16(unsigned dst, const void* src, bool valid) {
    int sz = valid ? 16 : 0;
    asm volatile("cp.async.cg.shared.global [%0], [%1], 16, %2;" :: "r"(dst), "l"(src), "r"(sz));
}
__device__ __forceinline__ void mma_f16(float4& d, const unsigned a[4], unsigned b0, unsigned b1) {
    asm volatile(
        "mma.sync.aligned.m16n8k16.row.col.f32.f16.f16.f32 "
        "{%0,%1,%2,%3}, {%4,%5,%6,%7}, {%8,%9}, {%0,%1,%2,%3};"
        : "+f"(d.x), "+f"(d.y), "+f"(d.z), "+f"(d.w)
        : "r"(a[0]), "r"(a[1]), "r"(a[2]), "r"(a[3]), "r"(b0), "r"(b1));
}
__device__ __forceinline__ void ldmx4(unsigned& r0, unsigned& r1, unsigned& r2, unsigned& r3,
                                      unsigned addr) {
    asm volatile("ldmatrix.sync.aligned.m8n8.x4.shared.b16 {%0,%1,%2,%3}, [%4];"
                 : "=r"(r0), "=r"(r1), "=r"(r2), "=r"(r3) : "r"(addr));
}
__device__ __forceinline__ void ldmx4t(unsigned& r0, unsigned& r1, unsigned& r2, unsigned& r3,
                                       unsigned addr) {
    asm volatile("ldmatrix.sync.aligned.m8n8.x4.trans.shared.b16 {%0,%1,%2,%3}, [%4];"
                 : "=r"(r0), "=r"(r1), "=r"(r2), "=r"(r3) : "r"(addr));
}

// ---------------- fp16 tensor-core GEMM (BK=64: half the barriers) ----------------
// C[m,n] = sum_k A[m,k] * B[n,k]  (A [M,K] h16 row-major, B [N,K] h16 row-major)
// K must be a multiple of 64 (768 and 3072 both are).
#define SH2 72   // smem row stride in halves (64 data + 8 pad)
template <bool BIAS, bool RES, bool SILU, bool OUTW, bool HOUT>
__global__ void __launch_bounds__(256, 1)
hgemm(const __half* __restrict__ A, const __half* __restrict__ B,
      void* __restrict__ Cv, const float* __restrict__ bias, const float* __restrict__ res,
      float* __restrict__ out2,
      int M, int N, int K, int lda, int ldb, int ldc) {
    const int NT = 8;
    __shared__ __half As[2][128 * SH2];
    __shared__ __half Bs[2][128 * SH2];

    int tid = threadIdx.x;
    int m0 = blockIdx.y * 128, n0 = blockIdx.x * 128;
    int warp = tid >> 5, lane = tid & 31;
    int wm = warp & 3, wn = warp >> 2;
    int mw = m0 + wm * 32;
    int nw = n0 + wn * 64;
    int g = lane >> 2, tg = lane & 3;

    float4 acc[2][NT];
    #pragma unroll
    for (int i = 0; i < 2; i++)
        #pragma unroll
        for (int j = 0; j < NT; j++) acc[i][j] = make_float4(0.f, 0.f, 0.f, 0.f);

    unsigned sA = smem_u32(As), sB = smem_u32(Bs);

    // ldmatrix lane offsets (in halves)
    int alm = ((lane & 7) + ((lane >> 3) & 1) * 8) * SH2 + (lane >> 4) * 8;
    int blm = ((lane & 7) + ((lane >> 4) & 1) * 8) * SH2 + ((lane >> 3) & 1) * 8;

    auto load_stage = [&](int ks, int buf) {   // ks in halves; 64 per stage
        #pragma unroll
        for (int i = 0; i < 4; i++) {
            int c = tid + i * 256;             // 0..1023
            int row = c >> 3, kc = (c & 7) << 3;
            unsigned dst = sA + (buf * 128 * SH2 + row * SH2 + kc) * 2;
            cp16(dst, A + (long long)(m0 + row) * lda + ks + kc, true);
        }
        #pragma unroll
        for (int i = 0; i < 4; i++) {
            int c = tid + i * 256;
            int row = c >> 3, kc = (c & 7) << 3;
            unsigned dst = sB + (buf * 128 * SH2 + row * SH2 + kc) * 2;
            cp16(dst, B + (long long)(n0 + row) * ldb + ks + kc, true);
        }
    };

    auto compute = [&](int buf) {
        unsigned abase = sA + (buf * 128 * SH2 + wm * 32 * SH2 + alm) * 2;
        unsigned bbase = sB + (buf * 128 * SH2 + wn * 64 * SH2 + blm) * 2;
        #pragma unroll
        for (int ks = 0; ks < 4; ks++) {       // four k16 steps per 64-half stage
            unsigned af[2][4];
            ldmx4(af[0][0], af[0][1], af[0][2], af[0][3], abase + (ks * 16) * 2);
            ldmx4(af[1][0], af[1][1], af[1][2], af[1][3], abase + (16 * SH2 + ks * 16) * 2);
            #pragma unroll
            for (int j0 = 0; j0 < NT; j0 += 2) {
                unsigned b0, b1, b2, b3;
                ldmx4(b0, b1, b2, b3, bbase + (8 * j0 * SH2 + ks * 16) * 2);
                mma_f16(acc[0][j0], af[0], b0, b1);
                mma_f16(acc[1][j0], af[1], b0, b1);
                mma_f16(acc[0][j0 + 1], af[0], b2, b3);
                mma_f16(acc[1][j0 + 1], af[1], b2, b3);
            }
        }
    };

    int numK = K >> 6;
    load_stage(0, 0);
    asm volatile("cp.async.commit_group;");
    for (int it = 0; it < numK; it++) {
        if (it + 1 < numK) {
            load_stage((it + 1) << 6, (it + 1) & 1);
            asm volatile("cp.async.commit_group;");
            asm volatile("cp.async.wait_group 1;");
        } else {
            asm volatile("cp.async.wait_group 0;");
        }
        __syncthreads();
        compute(it & 1);
        __syncthreads();
    }

    float* Cf = (float*)Cv;
    __half* Ch = (__half*)Cv;
    #pragma unroll
    for (int i = 0; i < 2; i++) {
        #pragma unroll
        for (int half_ = 0; half_ < 2; half_++) {
            int r = mw + i * 16 + g + half_ * 8;
            long long base = (long long)r * ldc;
            int bb = 0, l = 0;
            if (OUTW) { bb = r / L_TOT; l = r - bb * L_TOT; }
            #pragma unroll
            for (int j = 0; j < NT; j++) {
                float w0 = half_ ? acc[i][j].z : acc[i][j].x;
                float w1 = half_ ? acc[i][j].w : acc[i][j].y;
                int c0 = nw + j * 8 + tg * 2;
                if (BIAS) { w0 += bias[c0]; w1 += bias[c0 + 1]; }
                if (SILU) {
                    w0 = w0 / (1.f + __expf(-w0));
                    w1 = w1 / (1.f + __expf(-w1));
                }
                if (RES) { w0 += res[base + c0]; w1 += res[base + c0 + 1]; }
                if (HOUT) {
                    *(__half2*)(Ch + base + c0) = __floats2half2_rn(w0, w1);
                } else {
                    Cf[base + c0] = w0;
                    Cf[base + c0 + 1] = w1;
                }
                if (OUTW && l >= T_LEN) {
                    long long ob = ((long long)bb * T_LEN + (l - T_LEN)) * D_MODEL;
                    out2[ob + c0] = w0;
                    out2[ob + c0 + 1] = w1;
                }
            }
        }
    }
}

// ---------------- fused weight f32 -> f16 conversion ----------------
__global__ void cvt_all_kernel(const float* __restrict__ wqkv, const float* __restrict__ wout,
                               const float* __restrict__ w1, const float* __restrict__ w2,
                               __half* __restrict__ dst) {
    const int N0 = 884736, N1 = 294912, N2 = 1179648;
    const int E1 = N0 + N1, E2 = E1 + N2, TOT = E2 + N2;
    for (int i = blockIdx.x * 256 + threadIdx.x; i < TOT; i += gridDim.x * 256) {
        const float* src;
        int off;
        if (i < N0)        { src = wqkv; off = i; }
        else if (i < E1)   { src = wout; off = i - N0; }
        else if (i < E2)   { src = w1;   off = i - E1; }
        else               { src = w2;   off = i - E2; }
        float2 v = ((const float2*)src)[off];
        ((__half2*)dst)[i] = __floats2half2_rn(v.x, v.y);
    }
}

// ---------------- fused flash attention (R13-proven) ----------------
#define PADH 72
__global__ void __launch_bounds__(256, 2)
flash_attn(const __half* __restrict__ qkv, __half* __restrict__ ctx) {
    extern __shared__ __half smh[];
    __half* sP = smh;                       // 128 * PADH
    __half* sK = smh + 128 * PADH;          // 2 * 64 * PADH
    __half* sV = sK + 2 * 64 * PADH;        // 2 * 64 * PADH

    int tid = threadIdx.x;
    int warp = tid >> 5, lane = tid & 31;
    int g = lane >> 2, tg = lane & 3;
    int bh = blockIdx.y;
    int b = bh / N_HEADS, h = bh - b * N_HEADS;
    int m0 = blockIdx.x * 128;

    const __half* base = qkv + (long long)b * L_TOT * (3 * D_MODEL);
    const __half* Qp = base + h * 64;
    const __half* Kp = base + D_MODEL + h * 64;
    const __half* Vp = base + 2 * D_MODEL + h * 64;

    #pragma unroll
    for (int i = 0; i < 4; i++) {
        int c = tid + i * 256;
        int m = c >> 3, q = (c & 7) << 3;
        unsigned dst = smem_u32(sP + m * PADH + q);
        cp16(dst, Qp + (long long)(m0 + m) * (3 * D_MODEL) + q, (m0 + m) < L_TOT);
    }
    asm volatile("cp.async.commit_group;");
    asm volatile("cp.async.wait_group 0;");
    __syncthreads();

    unsigned qf[4][4];
    {
        const __half* qp = sP + (warp * 16) * PADH;
        #pragma unroll
        for (int ks = 0; ks < 4; ks++) {
            const __half* p = qp + g * PADH + 16 * ks + 2 * tg;
            qf[ks][0] = *(const unsigned*)p;
            qf[ks][1] = *(const unsigned*)(p + 8 * PADH);
            qf[ks][2] = *(const unsigned*)(p + 8);
            qf[ks][3] = *(const unsigned*)(p + 8 * PADH + 8);
        }
    }
    __syncthreads();

    int r0 = m0 + warp * 16 + g;
    int r1 = r0 + 8;
    int km0 = (r0 < T_LEN) ? L_TOT : ((r0 / NPATCH) + 1) * NPATCH;
    int km1 = (r1 < T_LEN) ? L_TOT : ((r1 / NPATCH) + 1) * NPATCH;

    float mrow0 = -1e30f, mrow1 = -1e30f, lrow0 = 0.f, lrow1 = 0.f;
    float4 accO[8];
    #pragma unroll
    for (int j = 0; j < 8; j++) accO[j] = make_float4(0.f, 0.f, 0.f, 0.f);

    int rlast = min(m0 + 127, L_TOT - 1);
    int kend = (m0 < T_LEN) ? L_TOT : ((rlast / NPATCH) + 1) * NPATCH;
    int ntiles = (kend + 63) >> 6;

    auto loadKV = [&](int t, int buf) {
        int n0t = t * 64;
        #pragma unroll
        for (int i = 0; i < 2; i++) {
            int c = tid + i * 256;
            int kv = c >> 3, q = (c & 7) << 3;
            bool ok = (n0t + kv) < L_TOT;
            long long goff = (long long)(n0t + kv) * (3 * D_MODEL) + q;
            cp16(smem_u32(sK + buf * 64 * PADH + kv * PADH + q), Kp + goff, ok);
            cp16(smem_u32(sV + buf * 64 * PADH + kv * PADH + q), Vp + goff, ok);
        }
    };

    loadKV(0, 0);
    asm volatile("cp.async.commit_group;");

    __half* pp = sP + (warp * 16) * PADH;
    int pa_off = ((lane & 7) + ((lane >> 3) & 1) * 8) * PADH + (lane >> 4) * 8;
    int vb_off = (lane & 15) * PADH + (lane >> 4) * 8;
    int kb_off = ((lane & 7) + ((lane >> 4) & 1) * 8) * PADH + ((lane >> 3) & 1) * 8;

    for (int t = 0; t < ntiles; t++) {
        int buf = t & 1;
        if (t + 1 < ntiles) {
            loadKV(t + 1, buf ^ 1);
            asm volatile("cp.async.commit_group;");
            asm volatile("cp.async.wait_group 1;");
        } else {
            asm volatile("cp.async.wait_group 0;");
        }
        __syncthreads();

        // S = Q @ K^T
        float4 s[8];
        #pragma unroll
        for (int j = 0; j < 8; j++) s[j] = make_float4(0.f, 0.f, 0.f, 0.f);
        unsigned kaddr = smem_u32(sK + buf * 64 * PADH) + kb_off * 2;
        #pragma unroll
        for (int ks = 0; ks < 4; ks++) {
            #pragma unroll
            for (int j0 = 0; j0 < 8; j0 += 2) {
                unsigned b0, b1, b2, b3;
                ldmx4(b0, b1, b2, b3, kaddr + (8 * j0 * PADH + 16 * ks) * 2);
                mma_f16(s[j0], qf[ks], b0, b1);
                mma_f16(s[j0 + 1], qf[ks], b2, b3);
            }
        }

        // scale + mask + online softmax
        float tmax0 = -1e30f, tmax1 = -1e30f;
        #pragma unroll
        for (int j = 0; j < 8; j++) {
            int c0 = t * 64 + 8 * j + 2 * tg;
            int c1 = c0 + 1;
            s[j].x = (c0 < km0) ? s[j].x * 0.125f : -1e30f;
            s[j].y = (c1 < km0) ? s[j].y * 0.125f : -1e30f;
            s[j].z = (c0 < km1) ? s[j].z * 0.125f : -1e30f;
            s[j].w = (c1 < km1) ? s[j].w * 0.125f : -1e30f;
            tmax0 = fmaxf(tmax0, fmaxf(s[j].x, s[j].y));
            tmax1 = fmaxf(tmax1, fmaxf(s[j].z, s[j].w));
        }
        tmax0 = fmaxf(tmax0, __shfl_xor_sync(0xffffffffu, tmax0, 1));
        tmax0 = fmaxf(tmax0, __shfl_xor_sync(0xffffffffu, tmax0, 2));
        tmax1 = fmaxf(tmax1, __shfl_xor_sync(0xffffffffu, tmax1, 1));
        tmax1 = fmaxf(tmax1, __shfl_xor_sync(0xffffffffu, tmax1, 2));

        float mn0 = fmaxf(mrow0, tmax0), mn1 = fmaxf(mrow1, tmax1);
        float al0 = __expf(mrow0 - mn0), al1 = __expf(mrow1 - mn1);
        mrow0 = mn0; mrow1 = mn1;

        float rs0 = 0.f, rs1 = 0.f;
        #pragma unroll
        for (int j = 0; j < 8; j++) {
            s[j].x = __expf(s[j].x - mn0);
            s[j].y = __expf(s[j].y - mn0);
            s[j].z = __expf(s[j].z - mn1);
            s[j].w = __expf(s[j].w - mn1);
            rs0 += s[j].x + s[j].y;
            rs1 += s[j].z + s[j].w;
            *(__half2*)&pp[g * PADH + 8 * j + 2 * tg] = __floats2half2_rn(s[j].x, s[j].y);
            *(__half2*)&pp[(g + 8) * PADH + 8 * j + 2 * tg] = __floats2half2_rn(s[j].z, s[j].w);
        }
        rs0 += __shfl_xor_sync(0xffffffffu, rs0, 1);
        rs0 += __shfl_xor_sync(0xffffffffu, rs0, 2);
        rs1 += __shfl_xor_sync(0xffffffffu, rs1, 1);
        rs1 += __shfl_xor_sync(0xffffffffu, rs1, 2);
        lrow0 = lrow0 * al0 + rs0;
        lrow1 = lrow1 * al1 + rs1;

        #pragma unroll
        for (int j = 0; j < 8; j++) {
            accO[j].x *= al0; accO[j].y *= al0;
            accO[j].z *= al1; accO[j].w *= al1;
        }
        __syncwarp();

        // O += P @ V via ldmatrix
        unsigned paddr = smem_u32(pp) + pa_off * 2;
        unsigned vaddr = smem_u32(sV + buf * 64 * PADH) + vb_off * 2;
        #pragma unroll
        for (int ks = 0; ks < 4; ks++) {
            unsigned af[4];
            ldmx4(af[0], af[1], af[2], af[3], paddr + 16 * ks * 2);
            #pragma unroll
            for (int jp = 0; jp < 4; jp++) {
                unsigned b0, b1, b2, b3;
                ldmx4t(b0, b1, b2, b3, vaddr + (16 * ks * PADH + 16 * jp) * 2);
                mma_f16(accO[2 * jp], af, b0, b1);
                mma_f16(accO[2 * jp + 1], af, b2, b3);
            }
        }
        __syncthreads();
    }

    float inv0 = 1.f / lrow0, inv1 = 1.f / lrow1;
    if (r0 < L_TOT) {
        __half* op = ctx + ((long long)b * L_TOT + r0) * D_MODEL + h * 64;
        #pragma unroll
        for (int j = 0; j < 8; j++)
            *(__half2*)&op[8 * j + 2 * tg] = __floats2half2_rn(accO[j].x * inv0, accO[j].y * inv0);
    }
    if (r1 < L_TOT) {
        __half* op = ctx + ((long long)b * L_TOT + r1) * D_MODEL + h * 64;
        #pragma unroll
        for (int j = 0; j < 8; j++)
            *(__half2*)&op[8 * j + 2 * tg] = __floats2half2_rn(accO[j].z * inv1, accO[j].w * inv1);
    }
}

// ---------------- layernorms: warp per row, shuffle reductions ----------------
__device__ __forceinline__ float wred(float v) {
    #pragma unroll
    for (int s = 16; s; s >>= 1) v += __shfl_xor_sync(0xffffffffu, v, s);
    return v;
}

__global__ void ln_build_kernel(const float* __restrict__ x,
                                const float* __restrict__ mem,
                                const float* __restrict__ g1, const float* __restrict__ b1,
                                const float* __restrict__ ga, const float* __restrict__ ba) {
    int warp = threadIdx.x >> 5, lane = threadIdx.x & 31;
    int row = blockIdx.x * 8 + warp;
    int b = row / L_TOT;
    int l = row - b * L_TOT;
    const float* src = (l < T_LEN)
        ? mem + ((long long)b * 1024 + l) * D_MODEL
        : x   + ((long long)b * T_LEN + (l - T_LEN)) * D_MODEL;

    float4 v[6];
    float sum = 0.f, sq = 0.f;
    #pragma unroll
    for (int i = 0; i < 6; i++) {
        v[i] = ((const float4*)src)[lane + 32 * i];
        sum += v[i].x + v[i].y + v[i].z + v[i].w;
        sq += v[i].x * v[i].x + v[i].y * v[i].y + v[i].z * v[i].z + v[i].w * v[i].w;
    }
    sum = wred(sum); sq = wred(sq);
    float mu = sum * (1.f / 768.f);
    float var = sq * (1.f / 768.f) - mu * mu;
    float rstd = rsqrtf(var + 1e-5f);

    float* xrow = g_xaug + (long long)row * D_MODEL;
    float w[6][4];
    float s2 = 0.f, q2 = 0.f;
    #pragma unroll
    for (int i = 0; i < 6; i++) {
        int c = (lane + 32 * i) * 4;
        float4 gv = *(const float4*)(g1 + c);
        float4 bv = *(const float4*)(b1 + c);
        w[i][0] = (v[i].x - mu) * rstd * gv.x + bv.x;
        w[i][1] = (v[i].y - mu) * rstd * gv.y + bv.y;
        w[i][2] = (v[i].z - mu) * rstd * gv.z + bv.z;
        w[i][3] = (v[i].w - mu) * rstd * gv.w + bv.w;
        *(float4*)(xrow + c) = make_float4(w[i][0], w[i][1], w[i][2], w[i][3]);
        s2 += w[i][0] + w[i][1] + w[i][2] + w[i][3];
        q2 += w[i][0] * w[i][0] + w[i][1] * w[i][1] + w[i][2] * w[i][2] + w[i][3] * w[i][3];
    }
    s2 = wred(s2); q2 = wred(q2);
    float mu2 = s2 * (1.f / 768.f);
    float var2 = q2 * (1.f / 768.f) - mu2 * mu2;
    float rstd2 = rsqrtf(var2 + 1e-5f);

    __half* hrow = g_h + (long long)row * D_MODEL;
    #pragma unroll
    for (int i = 0; i < 6; i++) {
        int c = (lane + 32 * i) * 4;
        float4 gv = *(const float4*)(ga + c);
        float4 bv = *(const float4*)(ba + c);
        __half2 h0 = __floats2half2_rn((w[i][0] - mu2) * rstd2 * gv.x + bv.x,
                                       (w[i][1] - mu2) * rstd2 * gv.y + bv.y);
        __half2 h1 = __floats2half2_rn((w[i][2] - mu2) * rstd2 * gv.z + bv.z,
                                       (w[i][3] - mu2) * rstd2 * gv.w + bv.w);
        *(__half2*)(hrow + c) = h0;
        *(__half2*)(hrow + c + 2) = h1;
    }
}

__global__ void ln_kernel(const float* __restrict__ src, __half* __restrict__ dst,
                          const float* __restrict__ g, const float* __restrict__ b) {
    int warp = threadIdx.x >> 5, lane = threadIdx.x & 31;
    int row = blockIdx.x * 8 + warp;
    const float* p = src + (long long)row * D_MODEL;

    float4 v[6];
    float sum = 0.f, sq = 0.f;
    #pragma unroll
    for (int i = 0; i < 6; i++) {
        v[i] = ((const float4*)p)[lane + 32 * i];
        sum += v[i].x + v[i].y + v[i].z + v[i].w;
        sq += v[i].x * v[i].x + v[i].y * v[i].y + v[i].z * v[i].z + v[i].w * v[i].w;
    }
    sum = wred(sum); sq = wred(sq);
    float mu = sum * (1.f / 768.f);
    float var = sq * (1.f / 768.f) - mu * mu;
    float rstd = rsqrtf(var + 1e-5f);

    __half* drow = dst + (long long)row * D_MODEL;
    #pragma unroll
    for (int i = 0; i < 6; i++) {
        int c = (lane + 32 * i) * 4;
        float4 gv = *(const float4*)(g + c);
        float4 bv = *(const float4*)(b + c);
        __half2 h0 = __floats2half2_rn((v[i].x - mu) * rstd * gv.x + bv.x,
                                       (v[i].y - mu) * rstd * gv.y + bv.y);
        __half2 h1 = __floats2half2_rn((v[i].z - mu) * rstd * gv.z + bv.z,
                                       (v[i].w - mu) * rstd * gv.w + bv.w);
        *(__half2*)(drow + c) = h0;
        *(__half2*)(drow + c + 2) = h1;
    }
}

// ---------------- launch ----------------
extern "C" void kernel_launch(void* const* d_in, const int* in_sizes, int n_in,
                              void* d_out, int out_size) {
    const float* x        = (const float*)d_in[0];
    const float* memory   = (const float*)d_in[1];
    const float* ln_att_g = (const float*)d_in[2];
    const float* ln_att_b = (const float*)d_in[3];
    const float* w_qkv    = (const float*)d_in[4];
    const float* w_out    = (const float*)d_in[5];
    const float* b_out    = (const float*)d_in[6];
    const float* ln1_g    = (const float*)d_in[7];
    const float* ln1_b    = (const float*)d_in[8];
    const float* ln2_g    = (const float*)d_in[9];
    const float* ln2_b    = (const float*)d_in[10];
    const float* w1       = (const float*)d_in[11];
    const float* b1       = (const float*)d_in[12];
    const float* w2       = (const float*)d_in[13];
    const float* b2       = (const float*)d_in[14];
    float* out = (float*)d_out;

    float* xaug;
    __half *h, *qkv, *ctx, *y2, *ff, *wh;
    cudaGetSymbolAddress((void**)&xaug, g_xaug);
    cudaGetSymbolAddress((void**)&h,    g_h);
    cudaGetSymbolAddress((void**)&qkv,  g_qkv);
    cudaGetSymbolAddress((void**)&ctx,  g_ctx);
    cudaGetSymbolAddress((void**)&y2,   g_y2);
    cudaGetSymbolAddress((void**)&ff,   g_ff);
    cudaGetSymbolAddress((void**)&wh,   g_whalf);

    __half* wqkv_h = wh;
    __half* wout_h = wh + 1769472;
    __half* w1_h   = wh + 2359296;
    __half* w2_h   = wh + 4718592;

    const int FLASH_SMEM = (128 * PADH + 4 * 64 * PADH) * 2;  // 55296 B
    cudaFuncSetAttribute(flash_attn, cudaFuncAttributeMaxDynamicSharedMemorySize, FLASH_SMEM);

    // 0) convert all weights to h16
    cvt_all_kernel<<<2048, 256>>>(w_qkv, w_out, w1, w2, wh);

    // 1) x_aug = ln1(concat(mem, x)) [f32]; h = ln_att(x_aug) [h16]
    ln_build_kernel<<<784, 256>>>(x, memory, ln1_g, ln1_b, ln_att_g, ln_att_b);

    // 2) qkv = h @ w_qkv^T  [h16]
    hgemm<false, false, false, false, true><<<dim3(18, 49), 256>>>(
        h, wqkv_h, qkv, nullptr, nullptr, nullptr,
        ROWS, 3 * D_MODEL, D_MODEL, D_MODEL, D_MODEL, 3 * D_MODEL);

    // 3-5) fused attention -> ctx [h16]
    flash_attn<<<dim3(13, 48), 256, FLASH_SMEM>>>(qkv, ctx);

    // 6) xaug += ctx @ w_out^T + b_out  [f32]
    hgemm<true, true, false, false, false><<<dim3(6, 49), 256>>>(
        ctx, wout_h, xaug, b_out, xaug, nullptr,
        ROWS, D_MODEL, D_MODEL, D_MODEL, D_MODEL, D_MODEL);

    // 7) y2 = ln2(xaug)  [h16]
    ln_kernel<<<784, 256>>>(xaug, y2, ln2_g, ln2_b);

    // 8) ff = silu(y2 @ w1^T + b1)  [h16]
    hgemm<true, false, true, false, true><<<dim3(24, 49), 256>>>(
        y2, w1_h, ff, b1, nullptr, nullptr,
        ROWS, D_FF, D_MODEL, D_MODEL, D_MODEL, D_FF);

    // 9) xaug += ff @ w2^T + b2 ; scatter x-rows to out  [f32]
    hgemm<true, true, false, true, false><<<dim3(6, 49), 256>>>(
        ff, w2_h, xaug, b2, xaug, out,
        ROWS, D_MODEL, D_FF, D_FF, D_FF, D_MODEL);
}

// round 16
// speedup vs baseline: 1.1984x; 1.0605x over previous
#include <cuda_runtime.h>
#include <cuda_fp16.h>
#include <math.h>
#include <stdint.h>

#define L_TOT 1568
#define T_LEN 784
#define D_MODEL 768
#define N_HEADS 12
#define DIM_HEAD 64
#define D_FF 3072
#define BATCH 4
#define ROWS (BATCH * L_TOT)          // 6272
#define NPATCH 196

// ---------------- scratch ----------------
__device__ float  g_xaug[ROWS * D_MODEL];          // residual stream (f32)
__device__ __half g_h[ROWS * D_MODEL];             // ln_att output (h16)
__device__ __half g_qkv[ROWS * 3 * D_MODEL];       // qkv (h16)
__device__ __half g_ctx[ROWS * D_MODEL];           // attention context (h16)
__device__ __half g_y2[ROWS * D_MODEL];            // ln2 output (h16)
__device__ __half g_ff[ROWS * D_FF];               // ff hidden (h16)
__device__ __half g_whalf[7077888];                // wqkv|wout|w1|w2 in h16

// ---------------- helpers ----------------
__device__ __forceinline__ unsigned smem_u32(const void* p) {
    unsigned r;
    asm("{ .reg .u64 t; cvta.to.shared.u64 t, %1; cvt.u32.u64 %0, t; }" : "=r"(r) : "l"(p));
    return r;
}
__device__ __forceinline__ void cp16(unsigned dst, const void* src, bool valid) {
    int sz = valid ? 16 : 0;
    asm volatile("cp.async.cg.shared.global [%0], [%1], 16, %2;" :: "r"(dst), "l"(src), "r"(sz));
}
__device__ __forceinline__ void mma_f16(float4& d, const unsigned a[4], unsigned b0, unsigned b1) {
    asm volatile(
        "mma.sync.aligned.m16n8k16.row.col.f32.f16.f16.f32 "
        "{%0,%1,%2,%3}, {%4,%5,%6,%7}, {%8,%9}, {%0,%1,%2,%3};"
        : "+f"(d.x), "+f"(d.y), "+f"(d.z), "+f"(d.w)
        : "r"(a[0]), "r"(a[1]), "r"(a[2]), "r"(a[3]), "r"(b0), "r"(b1));
}
__device__ __forceinline__ void ldmx4(unsigned& r0, unsigned& r1, unsigned& r2, unsigned& r3,
                                      unsigned addr) {
    asm volatile("ldmatrix.sync.aligned.m8n8.x4.shared.b16 {%0,%1,%2,%3}, [%4];"
                 : "=r"(r0), "=r"(r1), "=r"(r2), "=r"(r3) : "r"(addr));
}
__device__ __forceinline__ void ldmx4t(unsigned& r0, unsigned& r1, unsigned& r2, unsigned& r3,
                                       unsigned addr) {
    asm volatile("ldmatrix.sync.aligned.m8n8.x4.trans.shared.b16 {%0,%1,%2,%3}, [%4];"
                 : "=r"(r0), "=r"(r1), "=r"(r2), "=r"(r3) : "r"(addr));
}

// ---------------- fp16 tensor-core GEMM (BK=64, 3 stages, 1 barrier/iter) ----------------
// C[m,n] = sum_k A[m,k] * B[n,k]  (A [M,K] h16 row-major, B [N,K] h16 row-major)
// K must be a multiple of 64. Dynamic smem: 3 stages x (A+B) x 128 x SH2 halves.
#define SH2 72   // smem row stride in halves (64 data + 8 pad)
#define GSTG 3
#define GEMM_SMEM (GSTG * 2 * 128 * SH2 * 2)   // 110592 B
template <bool BIAS, bool RES, bool SILU, bool OUTW, bool HOUT>
__global__ void __launch_bounds__(256, 1)
hgemm(const __half* __restrict__ A, const __half* __restrict__ B,
      void* __restrict__ Cv, const float* __restrict__ bias, const float* __restrict__ res,
      float* __restrict__ out2,
      int M, int N, int K, int lda, int ldb, int ldc) {
    const int NT = 8;
    extern __shared__ __half gsm[];
    __half* As = gsm;                          // [GSTG][128*SH2]
    __half* Bs = gsm + GSTG * 128 * SH2;       // [GSTG][128*SH2]

    int tid = threadIdx.x;
    int m0 = blockIdx.y * 128, n0 = blockIdx.x * 128;
    int warp = tid >> 5, lane = tid & 31;
    int wm = warp & 3, wn = warp >> 2;
    int mw = m0 + wm * 32;
    int nw = n0 + wn * 64;
    int g = lane >> 2, tg = lane & 3;

    float4 acc[2][NT];
    #pragma unroll
    for (int i = 0; i < 2; i++)
        #pragma unroll
        for (int j = 0; j < NT; j++) acc[i][j] = make_float4(0.f, 0.f, 0.f, 0.f);

    unsigned sA = smem_u32(As), sB = smem_u32(Bs);

    // ldmatrix lane offsets (in halves)
    int alm = ((lane & 7) + ((lane >> 3) & 1) * 8) * SH2 + (lane >> 4) * 8;
    int blm = ((lane & 7) + ((lane >> 4) & 1) * 8) * SH2 + ((lane >> 3) & 1) * 8;

    auto load_stage = [&](int it, int buf) {   // loads 64-half K-chunk `it`
        int ks = it << 6;
        #pragma unroll
        for (int i = 0; i < 4; i++) {
            int c = tid + i * 256;
            int row = c >> 3, kc = (c & 7) << 3;
            unsigned dst = sA + (buf * 128 * SH2 + row * SH2 + kc) * 2;
            cp16(dst, A + (long long)(m0 + row) * lda + ks + kc, true);
        }
        #pragma unroll
        for (int i = 0; i < 4; i++) {
            int c = tid + i * 256;
            int row = c >> 3, kc = (c & 7) << 3;
            unsigned dst = sB + (buf * 128 * SH2 + row * SH2 + kc) * 2;
            cp16(dst, B + (long long)(n0 + row) * ldb + ks + kc, true);
        }
        asm volatile("cp.async.commit_group;");
    };

    auto compute = [&](int buf) {
        unsigned abase = sA + (buf * 128 * SH2 + wm * 32 * SH2 + alm) * 2;
        unsigned bbase = sB + (buf * 128 * SH2 + wn * 64 * SH2 + blm) * 2;
        #pragma unroll
        for (int ks = 0; ks < 4; ks++) {
            unsigned af[2][4];
            ldmx4(af[0][0], af[0][1], af[0][2], af[0][3], abase + (ks * 16) * 2);
            ldmx4(af[1][0], af[1][1], af[1][2], af[1][3], abase + (16 * SH2 + ks * 16) * 2);
            #pragma unroll
            for (int j0 = 0; j0 < NT; j0 += 2) {
                unsigned b0, b1, b2, b3;
                ldmx4(b0, b1, b2, b3, bbase + (8 * j0 * SH2 + ks * 16) * 2);
                mma_f16(acc[0][j0], af[0], b0, b1);
                mma_f16(acc[1][j0], af[1], b0, b1);
                mma_f16(acc[0][j0 + 1], af[0], b2, b3);
                mma_f16(acc[1][j0 + 1], af[1], b2, b3);
            }
        }
    };

    int numK = K >> 6;
    load_stage(0, 0);
    if (numK > 1) load_stage(1, 1);
    for (int it = 0; it < numK; it++) {
        if (it + 1 < numK) asm volatile("cp.async.wait_group 1;");
        else               asm volatile("cp.async.wait_group 0;");
        __syncthreads();
        compute(it % GSTG);
        if (it + 2 < numK) load_stage(it + 2, (it + 2) % GSTG);
    }

    float* Cf = (float*)Cv;
    __half* Ch = (__half*)Cv;
    #pragma unroll
    for (int i = 0; i < 2; i++) {
        #pragma unroll
        for (int half_ = 0; half_ < 2; half_++) {
            int r = mw + i * 16 + g + half_ * 8;
            long long base = (long long)r * ldc;
            int bb = 0, l = 0;
            if (OUTW) { bb = r / L_TOT; l = r - bb * L_TOT; }
            #pragma unroll
            for (int j = 0; j < NT; j++) {
                float w0 = half_ ? acc[i][j].z : acc[i][j].x;
                float w1 = half_ ? acc[i][j].w : acc[i][j].y;
                int c0 = nw + j * 8 + tg * 2;
                if (BIAS) { w0 += bias[c0]; w1 += bias[c0 + 1]; }
                if (SILU) {
                    w0 = w0 / (1.f + __expf(-w0));
                    w1 = w1 / (1.f + __expf(-w1));
                }
                if (RES) { w0 += res[base + c0]; w1 += res[base + c0 + 1]; }
                if (HOUT) {
                    *(__half2*)(Ch + base + c0) = __floats2half2_rn(w0, w1);
                } else {
                    Cf[base + c0] = w0;
                    Cf[base + c0 + 1] = w1;
                }
                if (OUTW && l >= T_LEN) {
                    long long ob = ((long long)bb * T_LEN + (l - T_LEN)) * D_MODEL;
                    out2[ob + c0] = w0;
                    out2[ob + c0 + 1] = w1;
                }
            }
        }
    }
}

// ---------------- fused weight f32 -> f16 conversion ----------------
__global__ void cvt_all_kernel(const float* __restrict__ wqkv, const float* __restrict__ wout,
                               const float* __restrict__ w1, const float* __restrict__ w2,
                               __half* __restrict__ dst) {
    const int N0 = 884736, N1 = 294912, N2 = 1179648;
    const int E1 = N0 + N1, E2 = E1 + N2, TOT = E2 + N2;
    for (int i = blockIdx.x * 256 + threadIdx.x; i < TOT; i += gridDim.x * 256) {
        const float* src;
        int off;
        if (i < N0)        { src = wqkv; off = i; }
        else if (i < E1)   { src = wout; off = i - N0; }
        else if (i < E2)   { src = w1;   off = i - E1; }
        else               { src = w2;   off = i - E2; }
        float2 v = ((const float2*)src)[off];
        ((__half2*)dst)[i] = __floats2half2_rn(v.x, v.y);
    }
}

// ---------------- fused flash attention (R13/R15-proven) ----------------
#define PADH 72
__global__ void __launch_bounds__(256, 2)
flash_attn(const __half* __restrict__ qkv, __half* __restrict__ ctx) {
    extern __shared__ __half smh[];
    __half* sP = smh;                       // 128 * PADH
    __half* sK = smh + 128 * PADH;          // 2 * 64 * PADH
    __half* sV = sK + 2 * 64 * PADH;        // 2 * 64 * PADH

    int tid = threadIdx.x;
    int warp = tid >> 5, lane = tid & 31;
    int g = lane >> 2, tg = lane & 3;
    int bh = blockIdx.y;
    int b = bh / N_HEADS, h = bh - b * N_HEADS;
    int m0 = blockIdx.x * 128;

    const __half* base = qkv + (long long)b * L_TOT * (3 * D_MODEL);
    const __half* Qp = base + h * 64;
    const __half* Kp = base + D_MODEL + h * 64;
    const __half* Vp = base + 2 * D_MODEL + h * 64;

    #pragma unroll
    for (int i = 0; i < 4; i++) {
        int c = tid + i * 256;
        int m = c >> 3, q = (c & 7) << 3;
        unsigned dst = smem_u32(sP + m * PADH + q);
        cp16(dst, Qp + (long long)(m0 + m) * (3 * D_MODEL) + q, (m0 + m) < L_TOT);
    }
    asm volatile("cp.async.commit_group;");
    asm volatile("cp.async.wait_group 0;");
    __syncthreads();

    unsigned qf[4][4];
    {
        const __half* qp = sP + (warp * 16) * PADH;
        #pragma unroll
        for (int ks = 0; ks < 4; ks++) {
            const __half* p = qp + g * PADH + 16 * ks + 2 * tg;
            qf[ks][0] = *(const unsigned*)p;
            qf[ks][1] = *(const unsigned*)(p + 8 * PADH);
            qf[ks][2] = *(const unsigned*)(p + 8);
            qf[ks][3] = *(const unsigned*)(p + 8 * PADH + 8);
        }
    }
    __syncthreads();

    int r0 = m0 + warp * 16 + g;
    int r1 = r0 + 8;
    int km0 = (r0 < T_LEN) ? L_TOT : ((r0 / NPATCH) + 1) * NPATCH;
    int km1 = (r1 < T_LEN) ? L_TOT : ((r1 / NPATCH) + 1) * NPATCH;

    float mrow0 = -1e30f, mrow1 = -1e30f, lrow0 = 0.f, lrow1 = 0.f;
    float4 accO[8];
    #pragma unroll
    for (int j = 0; j < 8; j++) accO[j] = make_float4(0.f, 0.f, 0.f, 0.f);

    int rlast = min(m0 + 127, L_TOT - 1);
    int kend = (m0 < T_LEN) ? L_TOT : ((rlast / NPATCH) + 1) * NPATCH;
    int ntiles = (kend + 63) >> 6;

    auto loadKV = [&](int t, int buf) {
        int n0t = t * 64;
        #pragma unroll
        for (int i = 0; i < 2; i++) {
            int c = tid + i * 256;
            int kv = c >> 3, q = (c & 7) << 3;
            bool ok = (n0t + kv) < L_TOT;
            long long goff = (long long)(n0t + kv) * (3 * D_MODEL) + q;
            cp16(smem_u32(sK + buf * 64 * PADH + kv * PADH + q), Kp + goff, ok);
            cp16(smem_u32(sV + buf * 64 * PADH + kv * PADH + q), Vp + goff, ok);
        }
    };

    loadKV(0, 0);
    asm volatile("cp.async.commit_group;");

    __half* pp = sP + (warp * 16) * PADH;
    int pa_off = ((lane & 7) + ((lane >> 3) & 1) * 8) * PADH + (lane >> 4) * 8;
    int vb_off = (lane & 15) * PADH + (lane >> 4) * 8;
    int kb_off = ((lane & 7) + ((lane >> 4) & 1) * 8) * PADH + ((lane >> 3) & 1) * 8;

    for (int t = 0; t < ntiles; t++) {
        int buf = t & 1;
        if (t + 1 < ntiles) {
            loadKV(t + 1, buf ^ 1);
            asm volatile("cp.async.commit_group;");
            asm volatile("cp.async.wait_group 1;");
        } else {
            asm volatile("cp.async.wait_group 0;");
        }
        __syncthreads();

        // S = Q @ K^T
        float4 s[8];
        #pragma unroll
        for (int j = 0; j < 8; j++) s[j] = make_float4(0.f, 0.f, 0.f, 0.f);
        unsigned kaddr = smem_u32(sK + buf * 64 * PADH) + kb_off * 2;
        #pragma unroll
        for (int ks = 0; ks < 4; ks++) {
            #pragma unroll
            for (int j0 = 0; j0 < 8; j0 += 2) {
                unsigned b0, b1, b2, b3;
                ldmx4(b0, b1, b2, b3, kaddr + (8 * j0 * PADH + 16 * ks) * 2);
                mma_f16(s[j0], qf[ks], b0, b1);
                mma_f16(s[j0 + 1], qf[ks], b2, b3);
            }
        }

        // scale + mask + online softmax
        float tmax0 = -1e30f, tmax1 = -1e30f;
        #pragma unroll
        for (int j = 0; j < 8; j++) {
            int c0 = t * 64 + 8 * j + 2 * tg;
            int c1 = c0 + 1;
            s[j].x = (c0 < km0) ? s[j].x * 0.125f : -1e30f;
            s[j].y = (c1 < km0) ? s[j].y * 0.125f : -1e30f;
            s[j].z = (c0 < km1) ? s[j].z * 0.125f : -1e30f;
            s[j].w = (c1 < km1) ? s[j].w * 0.125f : -1e30f;
            tmax0 = fmaxf(tmax0, fmaxf(s[j].x, s[j].y));
            tmax1 = fmaxf(tmax1, fmaxf(s[j].z, s[j].w));
        }
        tmax0 = fmaxf(tmax0, __shfl_xor_sync(0xffffffffu, tmax0, 1));
        tmax0 = fmaxf(tmax0, __shfl_xor_sync(0xffffffffu, tmax0, 2));
        tmax1 = fmaxf(tmax1, __shfl_xor_sync(0xffffffffu, tmax1, 1));
        tmax1 = fmaxf(tmax1, __shfl_xor_sync(0xffffffffu, tmax1, 2));

        float mn0 = fmaxf(mrow0, tmax0), mn1 = fmaxf(mrow1, tmax1);
        float al0 = __expf(mrow0 - mn0), al1 = __expf(mrow1 - mn1);
        mrow0 = mn0; mrow1 = mn1;

        float rs0 = 0.f, rs1 = 0.f;
        #pragma unroll
        for (int j = 0; j < 8; j++) {
            s[j].x = __expf(s[j].x - mn0);
            s[j].y = __expf(s[j].y - mn0);
            s[j].z = __expf(s[j].z - mn1);
            s[j].w = __expf(s[j].w - mn1);
            rs0 += s[j].x + s[j].y;
            rs1 += s[j].z + s[j].w;
            *(__half2*)&pp[g * PADH + 8 * j + 2 * tg] = __floats2half2_rn(s[j].x, s[j].y);
            *(__half2*)&pp[(g + 8) * PADH + 8 * j + 2 * tg] = __floats2half2_rn(s[j].z, s[j].w);
        }
        rs0 += __shfl_xor_sync(0xffffffffu, rs0, 1);
        rs0 += __shfl_xor_sync(0xffffffffu, rs0, 2);
        rs1 += __shfl_xor_sync(0xffffffffu, rs1, 1);
        rs1 += __shfl_xor_sync(0xffffffffu, rs1, 2);
        lrow0 = lrow0 * al0 + rs0;
        lrow1 = lrow1 * al1 + rs1;

        #pragma unroll
        for (int j = 0; j < 8; j++) {
            accO[j].x *= al0; accO[j].y *= al0;
            accO[j].z *= al1; accO[j].w *= al1;
        }
        __syncwarp();

        // O += P @ V via ldmatrix
        unsigned paddr = smem_u32(pp) + pa_off * 2;
        unsigned vaddr = smem_u32(sV + buf * 64 * PADH) + vb_off * 2;
        #pragma unroll
        for (int ks = 0; ks < 4; ks++) {
            unsigned af[4];
            ldmx4(af[0], af[1], af[2], af[3], paddr + 16 * ks * 2);
            #pragma unroll
            for (int jp = 0; jp < 4; jp++) {
                unsigned b0, b1, b2, b3;
                ldmx4t(b0, b1, b2, b3, vaddr + (16 * ks * PADH + 16 * jp) * 2);
                mma_f16(accO[2 * jp], af, b0, b1);
                mma_f16(accO[2 * jp + 1], af, b2, b3);
            }
        }
        __syncthreads();
    }

    float inv0 = 1.f / lrow0, inv1 = 1.f / lrow1;
    if (r0 < L_TOT) {
        __half* op = ctx + ((long long)b * L_TOT + r0) * D_MODEL + h * 64;
        #pragma unroll
        for (int j = 0; j < 8; j++)
            *(__half2*)&op[8 * j + 2 * tg] = __floats2half2_rn(accO[j].x * inv0, accO[j].y * inv0);
    }
    if (r1 < L_TOT) {
        __half* op = ctx + ((long long)b * L_TOT + r1) * D_MODEL + h * 64;
        #pragma unroll
        for (int j = 0; j < 8; j++)
            *(__half2*)&op[8 * j + 2 * tg] = __floats2half2_rn(accO[j].z * inv1, accO[j].w * inv1);
    }
}

// ---------------- layernorms: warp per row, shuffle reductions ----------------
__device__ __forceinline__ float wred(float v) {
    #pragma unroll
    for (int s = 16; s; s >>= 1) v += __shfl_xor_sync(0xffffffffu, v, s);
    return v;
}

__global__ void ln_build_kernel(const float* __restrict__ x,
                                const float* __restrict__ mem,
                                const float* __restrict__ g1, const float* __restrict__ b1,
                                const float* __restrict__ ga, const float* __restrict__ ba) {
    int warp = threadIdx.x >> 5, lane = threadIdx.x & 31;
    int row = blockIdx.x * 8 + warp;
    int b = row / L_TOT;
    int l = row - b * L_TOT;
    const float* src = (l < T_LEN)
        ? mem + ((long long)b * 1024 + l) * D_MODEL
        : x   + ((long long)b * T_LEN + (l - T_LEN)) * D_MODEL;

    float4 v[6];
    float sum = 0.f, sq = 0.f;
    #pragma unroll
    for (int i = 0; i < 6; i++) {
        v[i] = ((const float4*)src)[lane + 32 * i];
        sum += v[i].x + v[i].y + v[i].z + v[i].w;
        sq += v[i].x * v[i].x + v[i].y * v[i].y + v[i].z * v[i].z + v[i].w * v[i].w;
    }
    sum = wred(sum); sq = wred(sq);
    float mu = sum * (1.f / 768.f);
    float var = sq * (1.f / 768.f) - mu * mu;
    float rstd = rsqrtf(var + 1e-5f);

    float* xrow = g_xaug + (long long)row * D_MODEL;
    float w[6][4];
    float s2 = 0.f, q2 = 0.f;
    #pragma unroll
    for (int i = 0; i < 6; i++) {
        int c = (lane + 32 * i) * 4;
        float4 gv = *(const float4*)(g1 + c);
        float4 bv = *(const float4*)(b1 + c);
        w[i][0] = (v[i].x - mu) * rstd * gv.x + bv.x;
        w[i][1] = (v[i].y - mu) * rstd * gv.y + bv.y;
        w[i][2] = (v[i].z - mu) * rstd * gv.z + bv.z;
        w[i][3] = (v[i].w - mu) * rstd * gv.w + bv.w;
        *(float4*)(xrow + c) = make_float4(w[i][0], w[i][1], w[i][2], w[i][3]);
        s2 += w[i][0] + w[i][1] + w[i][2] + w[i][3];
        q2 += w[i][0] * w[i][0] + w[i][1] * w[i][1] + w[i][2] * w[i][2] + w[i][3] * w[i][3];
    }
    s2 = wred(s2); q2 = wred(q2);
    float mu2 = s2 * (1.f / 768.f);
    float var2 = q2 * (1.f / 768.f) - mu2 * mu2;
    float rstd2 = rsqrtf(var2 + 1e-5f);

    __half* hrow = g_h + (long long)row * D_MODEL;
    #pragma unroll
    for (int i = 0; i < 6; i++) {
        int c = (lane + 32 * i) * 4;
        float4 gv = *(const float4*)(ga + c);
        float4 bv = *(const float4*)(ba + c);
        __half2 h0 = __floats2half2_rn((w[i][0] - mu2) * rstd2 * gv.x + bv.x,
                                       (w[i][1] - mu2) * rstd2 * gv.y + bv.y);
        __half2 h1 = __floats2half2_rn((w[i][2] - mu2) * rstd2 * gv.z + bv.z,
                                       (w[i][3] - mu2) * rstd2 * gv.w + bv.w);
        *(__half2*)(hrow + c) = h0;
        *(__half2*)(hrow + c + 2) = h1;
    }
}

__global__ void ln_kernel(const float* __restrict__ src, __half* __restrict__ dst,
                          const float* __restrict__ g, const float* __restrict__ b) {
    int warp = threadIdx.x >> 5, lane = threadIdx.x & 31;
    int row = blockIdx.x * 8 + warp;
    const float* p = src + (long long)row * D_MODEL;

    float4 v[6];
    float sum = 0.f, sq = 0.f;
    #pragma unroll
    for (int i = 0; i < 6; i++) {
        v[i] = ((const float4*)p)[lane + 32 * i];
        sum += v[i].x + v[i].y + v[i].z + v[i].w;
        sq += v[i].x * v[i].x + v[i].y * v[i].y + v[i].z * v[i].z + v[i].w * v[i].w;
    }
    sum = wred(sum); sq = wred(sq);
    float mu = sum * (1.f / 768.f);
    float var = sq * (1.f / 768.f) - mu * mu;
    float rstd = rsqrtf(var + 1e-5f);

    __half* drow = dst + (long long)row * D_MODEL;
    #pragma unroll
    for (int i = 0; i < 6; i++) {
        int c = (lane + 32 * i) * 4;
        float4 gv = *(const float4*)(g + c);
        float4 bv = *(const float4*)(b + c);
        __half2 h0 = __floats2half2_rn((v[i].x - mu) * rstd * gv.x + bv.x,
                                       (v[i].y - mu) * rstd * gv.y + bv.y);
        __half2 h1 = __floats2half2_rn((v[i].z - mu) * rstd * gv.z + bv.z,
                                       (v[i].w - mu) * rstd * gv.w + bv.w);
        *(__half2*)(drow + c) = h0;
        *(__half2*)(drow + c + 2) = h1;
    }
}

// ---------------- launch ----------------
extern "C" void kernel_launch(void* const* d_in, const int* in_sizes, int n_in,
                              void* d_out, int out_size) {
    const float* x        = (const float*)d_in[0];
    const float* memory   = (const float*)d_in[1];
    const float* ln_att_g = (const float*)d_in[2];
    const float* ln_att_b = (const float*)d_in[3];
    const float* w_qkv    = (const float*)d_in[4];
    const float* w_out    = (const float*)d_in[5];
    const float* b_out    = (const float*)d_in[6];
    const float* ln1_g    = (const float*)d_in[7];
    const float* ln1_b    = (const float*)d_in[8];
    const float* ln2_g    = (const float*)d_in[9];
    const float* ln2_b    = (const float*)d_in[10];
    const float* w1       = (const float*)d_in[11];
    const float* b1       = (const float*)d_in[12];
    const float* w2       = (const float*)d_in[13];
    const float* b2       = (const float*)d_in[14];
    float* out = (float*)d_out;

    float* xaug;
    __half *h, *qkv, *ctx, *y2, *ff, *wh;
    cudaGetSymbolAddress((void**)&xaug, g_xaug);
    cudaGetSymbolAddress((void**)&h,    g_h);
    cudaGetSymbolAddress((void**)&qkv,  g_qkv);
    cudaGetSymbolAddress((void**)&ctx,  g_ctx);
    cudaGetSymbolAddress((void**)&y2,   g_y2);
    cudaGetSymbolAddress((void**)&ff,   g_ff);
    cudaGetSymbolAddress((void**)&wh,   g_whalf);

    __half* wqkv_h = wh;
    __half* wout_h = wh + 1769472;
    __half* w1_h   = wh + 2359296;
    __half* w2_h   = wh + 4718592;

    const int FLASH_SMEM = (128 * PADH + 4 * 64 * PADH) * 2;  // 55296 B
    cudaFuncSetAttribute(flash_attn, cudaFuncAttributeMaxDynamicSharedMemorySize, FLASH_SMEM);
    cudaFuncSetAttribute(hgemm<false, false, false, false, true>,
                         cudaFuncAttributeMaxDynamicSharedMemorySize, GEMM_SMEM);
    cudaFuncSetAttribute(hgemm<true, true, false, false, false>,
                         cudaFuncAttributeMaxDynamicSharedMemorySize, GEMM_SMEM);
    cudaFuncSetAttribute(hgemm<true, false, true, false, true>,
                         cudaFuncAttributeMaxDynamicSharedMemorySize, GEMM_SMEM);
    cudaFuncSetAttribute(hgemm<true, true, false, true, false>,
                         cudaFuncAttributeMaxDynamicSharedMemorySize, GEMM_SMEM);

    // 0) convert all weights to h16
    cvt_all_kernel<<<2048, 256>>>(w_qkv, w_out, w1, w2, wh);

    // 1) x_aug = ln1(concat(mem, x)) [f32]; h = ln_att(x_aug) [h16]
    ln_build_kernel<<<784, 256>>>(x, memory, ln1_g, ln1_b, ln_att_g, ln_att_b);

    // 2) qkv = h @ w_qkv^T  [h16]
    hgemm<false, false, false, false, true><<<dim3(18, 49), 256, GEMM_SMEM>>>(
        h, wqkv_h, qkv, nullptr, nullptr, nullptr,
        ROWS, 3 * D_MODEL, D_MODEL, D_MODEL, D_MODEL, 3 * D_MODEL);

    // 3-5) fused attention -> ctx [h16]
    flash_attn<<<dim3(13, 48), 256, FLASH_SMEM>>>(qkv, ctx);

    // 6) xaug += ctx @ w_out^T + b_out  [f32]
    hgemm<true, true, false, false, false><<<dim3(6, 49), 256, GEMM_SMEM>>>(
        ctx, wout_h, xaug, b_out, xaug, nullptr,
        ROWS, D_MODEL, D_MODEL, D_MODEL, D_MODEL, D_MODEL);

    // 7) y2 = ln2(xaug)  [h16]
    ln_kernel<<<784, 256>>>(xaug, y2, ln2_g, ln2_b);

    // 8) ff = silu(y2 @ w1^T + b1)  [h16]
    hgemm<true, false, true, false, true><<<dim3(24, 49), 256, GEMM_SMEM>>>(
        y2, w1_h, ff, b1, nullptr, nullptr,
        ROWS, D_FF, D_MODEL, D_MODEL, D_MODEL, D_FF);

    // 9) xaug += ff @ w2^T + b2 ; scatter x-rows to out  [f32]
    hgemm<true, true, false, true, false><<<dim3(6, 49), 256, GEMM_SMEM>>>(
        ff, w2_h, xaug, b2, xaug, out,
        ROWS, D_MODEL, D_FF, D_FF, D_FF, D_MODEL);
}

// round 17
// speedup vs baseline: 1.2133x; 1.0125x over previous
#include <cuda_runtime.h>
#include <cuda_fp16.h>
#include <math.h>
#include <stdint.h>

#define L_TOT 1568
#define T_LEN 784
#define D_MODEL 768
#define N_HEADS 12
#define DIM_HEAD 64
#define D_FF 3072
#define BATCH 4
#define ROWS (BATCH * L_TOT)          // 6272
#define NPATCH 196

// ---------------- scratch ----------------
__device__ float  g_xaug[ROWS * D_MODEL];          // residual stream (f32)
__device__ __half g_h[ROWS * D_MODEL];             // ln_att output (h16)
__device__ __half g_qkv[ROWS * 3 * D_MODEL];       // qkv (h16)
__device__ __half g_ctx[ROWS * D_MODEL];           // attention context (h16)
__device__ __half g_y2[ROWS * D_MODEL];            // ln2 output (h16)
__device__ __half g_ff[ROWS * D_FF];               // ff hidden (h16)
__device__ __half g_whalf[7077888];                // wqkv|wout|w1|w2 in h16

// ---------------- helpers ----------------
__device__ __forceinline__ unsigned smem_u32(const void* p) {
    unsigned r;
    asm("{ .reg .u64 t; cvta.to.shared.u64 t, %1; cvt.u32.u64 %0, t; }" : "=r"(r) : "l"(p));
    return r;
}
__device__ __forceinline__ void cp16(unsigned dst, const void* src, bool valid) {
    int sz = valid ? 16 : 0;
    asm volatile("cp.async.cg.shared.global [%0], [%1], 16, %2;" :: "r"(dst), "l"(src), "r"(sz));
}
__device__ __forceinline__ void mma_f16(float4& d, const unsigned a[4], unsigned b0, unsigned b1) {
    asm volatile(
        "mma.sync.aligned.m16n8k16.row.col.f32.f16.f16.f32 "
        "{%0,%1,%2,%3}, {%4,%5,%6,%7}, {%8,%9}, {%0,%1,%2,%3};"
        : "+f"(d.x), "+f"(d.y), "+f"(d.z), "+f"(d.w)
        : "r"(a[0]), "r"(a[1]), "r"(a[2]), "r"(a[3]), "r"(b0), "r"(b1));
}
__device__ __forceinline__ void ldmx4(unsigned& r0, unsigned& r1, unsigned& r2, unsigned& r3,
                                      unsigned addr) {
    asm volatile("ldmatrix.sync.aligned.m8n8.x4.shared.b16 {%0,%1,%2,%3}, [%4];"
                 : "=r"(r0), "=r"(r1), "=r"(r2), "=r"(r3) : "r"(addr));
}
__device__ __forceinline__ void ldmx4t(unsigned& r0, unsigned& r1, unsigned& r2, unsigned& r3,
                                       unsigned addr) {
    asm volatile("ldmatrix.sync.aligned.m8n8.x4.trans.shared.b16 {%0,%1,%2,%3}, [%4];"
                 : "=r"(r0), "=r"(r1), "=r"(r2), "=r"(r3) : "r"(addr));
}

// ---------------- fp16 tensor-core GEMM (R16-proven: BK=64, 3 stages, 1 barrier/iter) ----------------
#define SH2 72   // smem row stride in halves (64 data + 8 pad)
#define GSTG 3
#define GEMM_SMEM (GSTG * 2 * 128 * SH2 * 2)   // 110592 B
template <bool BIAS, bool RES, bool SILU, bool OUTW, bool HOUT>
__global__ void __launch_bounds__(256, 1)
hgemm(const __half* __restrict__ A, const __half* __restrict__ B,
      void* __restrict__ Cv, const float* __restrict__ bias, const float* __restrict__ res,
      float* __restrict__ out2,
      int M, int N, int K, int lda, int ldb, int ldc) {
    const int NT = 8;
    extern __shared__ __half gsm[];
    __half* As = gsm;
    __half* Bs = gsm + GSTG * 128 * SH2;

    int tid = threadIdx.x;
    int m0 = blockIdx.y * 128, n0 = blockIdx.x * 128;
    int warp = tid >> 5, lane = tid & 31;
    int wm = warp & 3, wn = warp >> 2;
    int mw = m0 + wm * 32;
    int nw = n0 + wn * 64;
    int g = lane >> 2, tg = lane & 3;

    float4 acc[2][NT];
    #pragma unroll
    for (int i = 0; i < 2; i++)
        #pragma unroll
        for (int j = 0; j < NT; j++) acc[i][j] = make_float4(0.f, 0.f, 0.f, 0.f);

    unsigned sA = smem_u32(As), sB = smem_u32(Bs);

    int alm = ((lane & 7) + ((lane >> 3) & 1) * 8) * SH2 + (lane >> 4) * 8;
    int blm = ((lane & 7) + ((lane >> 4) & 1) * 8) * SH2 + ((lane >> 3) & 1) * 8;

    auto load_stage = [&](int it, int buf) {
        int ks = it << 6;
        #pragma unroll
        for (int i = 0; i < 4; i++) {
            int c = tid + i * 256;
            int row = c >> 3, kc = (c & 7) << 3;
            unsigned dst = sA + (buf * 128 * SH2 + row * SH2 + kc) * 2;
            cp16(dst, A + (long long)(m0 + row) * lda + ks + kc, true);
        }
        #pragma unroll
        for (int i = 0; i < 4; i++) {
            int c = tid + i * 256;
            int row = c >> 3, kc = (c & 7) << 3;
            unsigned dst = sB + (buf * 128 * SH2 + row * SH2 + kc) * 2;
            cp16(dst, B + (long long)(n0 + row) * ldb + ks + kc, true);
        }
        asm volatile("cp.async.commit_group;");
    };

    auto compute = [&](int buf) {
        unsigned abase = sA + (buf * 128 * SH2 + wm * 32 * SH2 + alm) * 2;
        unsigned bbase = sB + (buf * 128 * SH2 + wn * 64 * SH2 + blm) * 2;
        #pragma unroll
        for (int ks = 0; ks < 4; ks++) {
            unsigned af[2][4];
            ldmx4(af[0][0], af[0][1], af[0][2], af[0][3], abase + (ks * 16) * 2);
            ldmx4(af[1][0], af[1][1], af[1][2], af[1][3], abase + (16 * SH2 + ks * 16) * 2);
            #pragma unroll
            for (int j0 = 0; j0 < NT; j0 += 2) {
                unsigned b0, b1, b2, b3;
                ldmx4(b0, b1, b2, b3, bbase + (8 * j0 * SH2 + ks * 16) * 2);
                mma_f16(acc[0][j0], af[0], b0, b1);
                mma_f16(acc[1][j0], af[1], b0, b1);
                mma_f16(acc[0][j0 + 1], af[0], b2, b3);
                mma_f16(acc[1][j0 + 1], af[1], b2, b3);
            }
        }
    };

    int numK = K >> 6;
    load_stage(0, 0);
    if (numK > 1) load_stage(1, 1);
    for (int it = 0; it < numK; it++) {
        if (it + 1 < numK) asm volatile("cp.async.wait_group 1;");
        else               asm volatile("cp.async.wait_group 0;");
        __syncthreads();
        compute(it % GSTG);
        if (it + 2 < numK) load_stage(it + 2, (it + 2) % GSTG);
    }

    float* Cf = (float*)Cv;
    __half* Ch = (__half*)Cv;
    #pragma unroll
    for (int i = 0; i < 2; i++) {
        #pragma unroll
        for (int half_ = 0; half_ < 2; half_++) {
            int r = mw + i * 16 + g + half_ * 8;
            long long base = (long long)r * ldc;
            int bb = 0, l = 0;
            if (OUTW) { bb = r / L_TOT; l = r - bb * L_TOT; }
            #pragma unroll
            for (int j = 0; j < NT; j++) {
                float w0 = half_ ? acc[i][j].z : acc[i][j].x;
                float w1 = half_ ? acc[i][j].w : acc[i][j].y;
                int c0 = nw + j * 8 + tg * 2;
                if (BIAS) { w0 += bias[c0]; w1 += bias[c0 + 1]; }
                if (SILU) {
                    w0 = w0 / (1.f + __expf(-w0));
                    w1 = w1 / (1.f + __expf(-w1));
                }
                if (RES) { w0 += res[base + c0]; w1 += res[base + c0 + 1]; }
                if (HOUT) {
                    *(__half2*)(Ch + base + c0) = __floats2half2_rn(w0, w1);
                } else {
                    Cf[base + c0] = w0;
                    Cf[base + c0 + 1] = w1;
                }
                if (OUTW && l >= T_LEN) {
                    long long ob = ((long long)bb * T_LEN + (l - T_LEN)) * D_MODEL;
                    out2[ob + c0] = w0;
                    out2[ob + c0 + 1] = w1;
                }
            }
        }
    }
}

// ---------------- fused weight f32 -> f16 conversion ----------------
__global__ void cvt_all_kernel(const float* __restrict__ wqkv, const float* __restrict__ wout,
                               const float* __restrict__ w1, const float* __restrict__ w2,
                               __half* __restrict__ dst) {
    const int N0 = 884736, N1 = 294912, N2 = 1179648;
    const int E1 = N0 + N1, E2 = E1 + N2, TOT = E2 + N2;
    for (int i = blockIdx.x * 256 + threadIdx.x; i < TOT; i += gridDim.x * 256) {
        const float* src;
        int off;
        if (i < N0)        { src = wqkv; off = i; }
        else if (i < E1)   { src = wout; off = i - N0; }
        else if (i < E2)   { src = w1;   off = i - E1; }
        else               { src = w2;   off = i - E2; }
        float2 v = ((const float2*)src)[off];
        ((__half2*)dst)[i] = __floats2half2_rn(v.x, v.y);
    }
}

// ---------------- fused flash attention (3-stage KV, 1 barrier/tile) ----------------
#define PADH 72
#define FSTG 3
#define FLASH_SMEM ((128 * PADH + FSTG * 2 * 64 * PADH) * 2)   // 73728 B
__global__ void __launch_bounds__(256, 2)
flash_attn(const __half* __restrict__ qkv, __half* __restrict__ ctx) {
    extern __shared__ __half smh[];
    __half* sP = smh;                       // 128 * PADH
    __half* sK = smh + 128 * PADH;          // FSTG * 64 * PADH
    __half* sV = sK + FSTG * 64 * PADH;     // FSTG * 64 * PADH

    int tid = threadIdx.x;
    int warp = tid >> 5, lane = tid & 31;
    int g = lane >> 2, tg = lane & 3;
    int bh = blockIdx.y;
    int b = bh / N_HEADS, h = bh - b * N_HEADS;
    int m0 = blockIdx.x * 128;

    const __half* base = qkv + (long long)b * L_TOT * (3 * D_MODEL);
    const __half* Qp = base + h * 64;
    const __half* Kp = base + D_MODEL + h * 64;
    const __half* Vp = base + 2 * D_MODEL + h * 64;

    #pragma unroll
    for (int i = 0; i < 4; i++) {
        int c = tid + i * 256;
        int m = c >> 3, q = (c & 7) << 3;
        unsigned dst = smem_u32(sP + m * PADH + q);
        cp16(dst, Qp + (long long)(m0 + m) * (3 * D_MODEL) + q, (m0 + m) < L_TOT);
    }
    asm volatile("cp.async.commit_group;");

    int rlast = min(m0 + 127, L_TOT - 1);
    int kend = (m0 < T_LEN) ? L_TOT : ((rlast / NPATCH) + 1) * NPATCH;
    int ntiles = (kend + 63) >> 6;

    auto loadKV = [&](int t, int buf) {
        int n0t = t * 64;
        #pragma unroll
        for (int i = 0; i < 2; i++) {
            int c = tid + i * 256;
            int kv = c >> 3, q = (c & 7) << 3;
            bool ok = (n0t + kv) < L_TOT;
            long long goff = (long long)(n0t + kv) * (3 * D_MODEL) + q;
            cp16(smem_u32(sK + buf * 64 * PADH + kv * PADH + q), Kp + goff, ok);
            cp16(smem_u32(sV + buf * 64 * PADH + kv * PADH + q), Vp + goff, ok);
        }
        asm volatile("cp.async.commit_group;");
    };

    loadKV(0, 0);
    if (ntiles > 1) loadKV(1, 1);

    // wait for Q (all groups include it; safe to over-wait here once)
    asm volatile("cp.async.wait_group 2;");   // Q group done when >= 2 groups pending allowed... (Q is oldest)
    // NOTE: Q group is the first committed; with 2 KV groups also committed, wait_group 2 retires Q.
    __syncthreads();

    unsigned qf[4][4];
    {
        const __half* qp = sP + (warp * 16) * PADH;
        #pragma unroll
        for (int ks = 0; ks < 4; ks++) {
            const __half* p = qp + g * PADH + 16 * ks + 2 * tg;
            qf[ks][0] = *(const unsigned*)p;
            qf[ks][1] = *(const unsigned*)(p + 8 * PADH);
            qf[ks][2] = *(const unsigned*)(p + 8);
            qf[ks][3] = *(const unsigned*)(p + 8 * PADH + 8);
        }
    }
    __syncthreads();   // all warps done reading Q before sP reused for P

    int r0 = m0 + warp * 16 + g;
    int r1 = r0 + 8;
    int km0 = (r0 < T_LEN) ? L_TOT : ((r0 / NPATCH) + 1) * NPATCH;
    int km1 = (r1 < T_LEN) ? L_TOT : ((r1 / NPATCH) + 1) * NPATCH;

    float mrow0 = -1e30f, mrow1 = -1e30f, lrow0 = 0.f, lrow1 = 0.f;
    float4 accO[8];
    #pragma unroll
    for (int j = 0; j < 8; j++) accO[j] = make_float4(0.f, 0.f, 0.f, 0.f);

    __half* pp = sP + (warp * 16) * PADH;
    int pa_off = ((lane & 7) + ((lane >> 3) & 1) * 8) * PADH + (lane >> 4) * 8;
    int vb_off = (lane & 15) * PADH + (lane >> 4) * 8;
    int kb_off = ((lane & 7) + ((lane >> 4) & 1) * 8) * PADH + ((lane >> 3) & 1) * 8;

    for (int t = 0; t < ntiles; t++) {
        int buf = t % FSTG;
        if (t + 1 < ntiles) asm volatile("cp.async.wait_group 1;");
        else                asm volatile("cp.async.wait_group 0;");
        __syncthreads();

        // S = Q @ K^T
        float4 s[8];
        #pragma unroll
        for (int j = 0; j < 8; j++) s[j] = make_float4(0.f, 0.f, 0.f, 0.f);
        unsigned kaddr = smem_u32(sK + buf * 64 * PADH) + kb_off * 2;
        #pragma unroll
        for (int ks = 0; ks < 4; ks++) {
            #pragma unroll
            for (int j0 = 0; j0 < 8; j0 += 2) {
                unsigned b0, b1, b2, b3;
                ldmx4(b0, b1, b2, b3, kaddr + (8 * j0 * PADH + 16 * ks) * 2);
                mma_f16(s[j0], qf[ks], b0, b1);
                mma_f16(s[j0 + 1], qf[ks], b2, b3);
            }
        }

        // scale + mask + online softmax
        float tmax0 = -1e30f, tmax1 = -1e30f;
        #pragma unroll
        for (int j = 0; j < 8; j++) {
            int c0 = t * 64 + 8 * j + 2 * tg;
            int c1 = c0 + 1;
            s[j].x = (c0 < km0) ? s[j].x * 0.125f : -1e30f;
            s[j].y = (c1 < km0) ? s[j].y * 0.125f : -1e30f;
            s[j].z = (c0 < km1) ? s[j].z * 0.125f : -1e30f;
            s[j].w = (c1 < km1) ? s[j].w * 0.125f : -1e30f;
            tmax0 = fmaxf(tmax0, fmaxf(s[j].x, s[j].y));
            tmax1 = fmaxf(tmax1, fmaxf(s[j].z, s[j].w));
        }
        tmax0 = fmaxf(tmax0, __shfl_xor_sync(0xffffffffu, tmax0, 1));
        tmax0 = fmaxf(tmax0, __shfl_xor_sync(0xffffffffu, tmax0, 2));
        tmax1 = fmaxf(tmax1, __shfl_xor_sync(0xffffffffu, tmax1, 1));
        tmax1 = fmaxf(tmax1, __shfl_xor_sync(0xffffffffu, tmax1, 2));

        float mn0 = fmaxf(mrow0, tmax0), mn1 = fmaxf(mrow1, tmax1);
        float al0 = __expf(mrow0 - mn0), al1 = __expf(mrow1 - mn1);
        mrow0 = mn0; mrow1 = mn1;

        float rs0 = 0.f, rs1 = 0.f;
        #pragma unroll
        for (int j = 0; j < 8; j++) {
            s[j].x = __expf(s[j].x - mn0);
            s[j].y = __expf(s[j].y - mn0);
            s[j].z = __expf(s[j].z - mn1);
            s[j].w = __expf(s[j].w - mn1);
            rs0 += s[j].x + s[j].y;
            rs1 += s[j].z + s[j].w;
            *(__half2*)&pp[g * PADH + 8 * j + 2 * tg] = __floats2half2_rn(s[j].x, s[j].y);
            *(__half2*)&pp[(g + 8) * PADH + 8 * j + 2 * tg] = __floats2half2_rn(s[j].z, s[j].w);
        }
        rs0 += __shfl_xor_sync(0xffffffffu, rs0, 1);
        rs0 += __shfl_xor_sync(0xffffffffu, rs0, 2);
        rs1 += __shfl_xor_sync(0xffffffffu, rs1, 1);
        rs1 += __shfl_xor_sync(0xffffffffu, rs1, 2);
        lrow0 = lrow0 * al0 + rs0;
        lrow1 = lrow1 * al1 + rs1;

        #pragma unroll
        for (int j = 0; j < 8; j++) {
            accO[j].x *= al0; accO[j].y *= al0;
            accO[j].z *= al1; accO[j].w *= al1;
        }
        __syncwarp();

        // O += P @ V via ldmatrix
        unsigned paddr = smem_u32(pp) + pa_off * 2;
        unsigned vaddr = smem_u32(sV + buf * 64 * PADH) + vb_off * 2;
        #pragma unroll
        for (int ks = 0; ks < 4; ks++) {
            unsigned af[4];
            ldmx4(af[0], af[1], af[2], af[3], paddr + 16 * ks * 2);
            #pragma unroll
            for (int jp = 0; jp < 4; jp++) {
                unsigned b0, b1, b2, b3;
                ldmx4t(b0, b1, b2, b3, vaddr + (16 * ks * PADH + 16 * jp) * 2);
                mma_f16(accO[2 * jp], af, b0, b1);
                mma_f16(accO[2 * jp + 1], af, b2, b3);
            }
        }

        if (t + 2 < ntiles) loadKV(t + 2, (t + 2) % FSTG);
    }

    float inv0 = 1.f / lrow0, inv1 = 1.f / lrow1;
    if (r0 < L_TOT) {
        __half* op = ctx + ((long long)b * L_TOT + r0) * D_MODEL + h * 64;
        #pragma unroll
        for (int j = 0; j < 8; j++)
            *(__half2*)&op[8 * j + 2 * tg] = __floats2half2_rn(accO[j].x * inv0, accO[j].y * inv0);
    }
    if (r1 < L_TOT) {
        __half* op = ctx + ((long long)b * L_TOT + r1) * D_MODEL + h * 64;
        #pragma unroll
        for (int j = 0; j < 8; j++)
            *(__half2*)&op[8 * j + 2 * tg] = __floats2half2_rn(accO[j].z * inv1, accO[j].w * inv1);
    }
}

// ---------------- layernorms: warp per row, shuffle reductions ----------------
__device__ __forceinline__ float wred(float v) {
    #pragma unroll
    for (int s = 16; s; s >>= 1) v += __shfl_xor_sync(0xffffffffu, v, s);
    return v;
}

__global__ void ln_build_kernel(const float* __restrict__ x,
                                const float* __restrict__ mem,
                                const float* __restrict__ g1, const float* __restrict__ b1,
                                const float* __restrict__ ga, const float* __restrict__ ba) {
    int warp = threadIdx.x >> 5, lane = threadIdx.x & 31;
    int row = blockIdx.x * 8 + warp;
    int b = row / L_TOT;
    int l = row - b * L_TOT;
    const float* src = (l < T_LEN)
        ? mem + ((long long)b * 1024 + l) * D_MODEL
        : x   + ((long long)b * T_LEN + (l - T_LEN)) * D_MODEL;

    float4 v[6];
    float sum = 0.f, sq = 0.f;
    #pragma unroll
    for (int i = 0; i < 6; i++) {
        v[i] = ((const float4*)src)[lane + 32 * i];
        sum += v[i].x + v[i].y + v[i].z + v[i].w;
        sq += v[i].x * v[i].x + v[i].y * v[i].y + v[i].z * v[i].z + v[i].w * v[i].w;
    }
    sum = wred(sum); sq = wred(sq);
    float mu = sum * (1.f / 768.f);
    float var = sq * (1.f / 768.f) - mu * mu;
    float rstd = rsqrtf(var + 1e-5f);

    float* xrow = g_xaug + (long long)row * D_MODEL;
    float w[6][4];
    float s2 = 0.f, q2 = 0.f;
    #pragma unroll
    for (int i = 0; i < 6; i++) {
        int c = (lane + 32 * i) * 4;
        float4 gv = *(const float4*)(g1 + c);
        float4 bv = *(const float4*)(b1 + c);
        w[i][0] = (v[i].x - mu) * rstd * gv.x + bv.x;
        w[i][1] = (v[i].y - mu) * rstd * gv.y + bv.y;
        w[i][2] = (v[i].z - mu) * rstd * gv.z + bv.z;
        w[i][3] = (v[i].w - mu) * rstd * gv.w + bv.w;
        *(float4*)(xrow + c) = make_float4(w[i][0], w[i][1], w[i][2], w[i][3]);
        s2 += w[i][0] + w[i][1] + w[i][2] + w[i][3];
        q2 += w[i][0] * w[i][0] + w[i][1] * w[i][1] + w[i][2] * w[i][2] + w[i][3] * w[i][3];
    }
    s2 = wred(s2); q2 = wred(q2);
    float mu2 = s2 * (1.f / 768.f);
    float var2 = q2 * (1.f / 768.f) - mu2 * mu2;
    float rstd2 = rsqrtf(var2 + 1e-5f);

    __half* hrow = g_h + (long long)row * D_MODEL;
    #pragma unroll
    for (int i = 0; i < 6; i++) {
        int c = (lane + 32 * i) * 4;
        float4 gv = *(const float4*)(ga + c);
        float4 bv = *(const float4*)(ba + c);
        __half2 h0 = __floats2half2_rn((w[i][0] - mu2) * rstd2 * gv.x + bv.x,
                                       (w[i][1] - mu2) * rstd2 * gv.y + bv.y);
        __half2 h1 = __floats2half2_rn((w[i][2] - mu2) * rstd2 * gv.z + bv.z,
                                       (w[i][3] - mu2) * rstd2 * gv.w + bv.w);
        *(__half2*)(hrow + c) = h0;
        *(__half2*)(hrow + c + 2) = h1;
    }
}

__global__ void ln_kernel(const float* __restrict__ src, __half* __restrict__ dst,
                          const float* __restrict__ g, const float* __restrict__ b) {
    int warp = threadIdx.x >> 5, lane = threadIdx.x & 31;
    int row = blockIdx.x * 8 + warp;
    const float* p = src + (long long)row * D_MODEL;

    float4 v[6];
    float sum = 0.f, sq = 0.f;
    #pragma unroll
    for (int i = 0; i < 6; i++) {
        v[i] = ((const float4*)p)[lane + 32 * i];
        sum += v[i].x + v[i].y + v[i].z + v[i].w;
        sq += v[i].x * v[i].x + v[i].y * v[i].y + v[i].z * v[i].z + v[i].w * v[i].w;
    }
    sum = wred(sum); sq = wred(sq);
    float mu = sum * (1.f / 768.f);
    float var = sq * (1.f / 768.f) - mu * mu;
    float rstd = rsqrtf(var + 1e-5f);

    __half* drow = dst + (long long)row * D_MODEL;
    #pragma unroll
    for (int i = 0; i < 6; i++) {
        int c = (lane + 32 * i) * 4;
        float4 gv = *(const float4*)(g + c);
        float4 bv = *(const float4*)(b + c);
        __half2 h0 = __floats2half2_rn((v[i].x - mu) * rstd * gv.x + bv.x,
                                       (v[i].y - mu) * rstd * gv.y + bv.y);
        __half2 h1 = __floats2half2_rn((v[i].z - mu) * rstd * gv.z + bv.z,
                                       (v[i].w - mu) * rstd * gv.w + bv.w);
        *(__half2*)(drow + c) = h0;
        *(__half2*)(drow + c + 2) = h1;
    }
}

// ---------------- launch ----------------
extern "C" void kernel_launch(void* const* d_in, const int* in_sizes, int n_in,
                              void* d_out, int out_size) {
    const float* x        = (const float*)d_in[0];
    const float* memory   = (const float*)d_in[1];
    const float* ln_att_g = (const float*)d_in[2];
    const float* ln_att_b = (const float*)d_in[3];
    const float* w_qkv    = (const float*)d_in[4];
    const float* w_out    = (const float*)d_in[5];
    const float* b_out    = (const float*)d_in[6];
    const float* ln1_g    = (const float*)d_in[7];
    const float* ln1_b    = (const float*)d_in[8];
    const float* ln2_g    = (const float*)d_in[9];
    const float* ln2_b    = (const float*)d_in[10];
    const float* w1       = (const float*)d_in[11];
    const float* b1       = (const float*)d_in[12];
    const float* w2       = (const float*)d_in[13];
    const float* b2       = (const float*)d_in[14];
    float* out = (float*)d_out;

    float* xaug;
    __half *h, *qkv, *ctx, *y2, *ff, *wh;
    cudaGetSymbolAddress((void**)&xaug, g_xaug);
    cudaGetSymbolAddress((void**)&h,    g_h);
    cudaGetSymbolAddress((void**)&qkv,  g_qkv);
    cudaGetSymbolAddress((void**)&ctx,  g_ctx);
    cudaGetSymbolAddress((void**)&y2,   g_y2);
    cudaGetSymbolAddress((void**)&ff,   g_ff);
    cudaGetSymbolAddress((void**)&wh,   g_whalf);

    __half* wqkv_h = wh;
    __half* wout_h = wh + 1769472;
    __half* w1_h   = wh + 2359296;
    __half* w2_h   = wh + 4718592;

    cudaFuncSetAttribute(flash_attn, cudaFuncAttributeMaxDynamicSharedMemorySize, FLASH_SMEM);
    cudaFuncSetAttribute(hgemm<false, false, false, false, true>,
                         cudaFuncAttributeMaxDynamicSharedMemorySize, GEMM_SMEM);
    cudaFuncSetAttribute(hgemm<true, true, false, false, false>,
                         cudaFuncAttributeMaxDynamicSharedMemorySize, GEMM_SMEM);
    cudaFuncSetAttribute(hgemm<true, false, true, false, true>,
                         cudaFuncAttributeMaxDynamicSharedMemorySize, GEMM_SMEM);
    cudaFuncSetAttribute(hgemm<true, true, false, true, false>,
                         cudaFuncAttributeMaxDynamicSharedMemorySize, GEMM_SMEM);

    // 0) convert all weights to h16
    cvt_all_kernel<<<2048, 256>>>(w_qkv, w_out, w1, w2, wh);

    // 1) x_aug = ln1(concat(mem, x)) [f32]; h = ln_att(x_aug) [h16]
    ln_build_kernel<<<784, 256>>>(x, memory, ln1_g, ln1_b, ln_att_g, ln_att_b);

    // 2) qkv = h @ w_qkv^T  [h16]
    hgemm<false, false, false, false, true><<<dim3(18, 49), 256, GEMM_SMEM>>>(
        h, wqkv_h, qkv, nullptr, nullptr, nullptr,
        ROWS, 3 * D_MODEL, D_MODEL, D_MODEL, D_MODEL, 3 * D_MODEL);

    // 3-5) fused attention -> ctx [h16]
    flash_attn<<<dim3(13, 48), 256, FLASH_SMEM>>>(qkv, ctx);

    // 6) xaug += ctx @ w_out^T + b_out  [f32]
    hgemm<true, true, false, false, false><<<dim3(6, 49), 256, GEMM_SMEM>>>(
        ctx, wout_h, xaug, b_out, xaug, nullptr,
        ROWS, D_MODEL, D_MODEL, D_MODEL, D_MODEL, D_MODEL);

    // 7) y2 = ln2(xaug)  [h16]
    ln_kernel<<<784, 256>>>(xaug, y2, ln2_g, ln2_b);

    // 8) ff = silu(y2 @ w1^T + b1)  [h16]
    hgemm<true, false, true, false, true><<<dim3(24, 49), 256, GEMM_SMEM>>>(
        y2, w1_h, ff, b1, nullptr, nullptr,
        ROWS, D_FF, D_MODEL, D_MODEL, D_MODEL, D_FF);

    // 9) xaug += ff @ w2^T + b2 ; scatter x-rows to out  [f32]
    hgemm<true, true, false, true, false><<<dim3(6, 49), 256, GEMM_SMEM>>>(
        ff, w2_h, xaug, b2, xaug, out,
        ROWS, D_MODEL, D_FF, D_FF, D_FF, D_MODEL);
}